// round 8
// baseline (speedup 1.0000x reference)
#include <cuda_runtime.h>
#include <stdint.h>
#include <math.h>

#define HEADS 8
#define HW 64
#define D 32
#define NTOK 4096
#define DIMX 256
#define INCDIM 768
#define NSTAGE 6
#define MB 4

// ---------------- scratch (static device globals; no allocation) -------------
__device__ float g_Q[HEADS * NTOK * D];                 // 4 MB
__device__ float g_K[HEADS * NTOK * D];                 // 4 MB
__device__ float g_V[HEADS * NTOK * D];                 // 4 MB
__device__ float g_U[(size_t)HEADS * HW * HW * D * D];  // 134 MB row-cumsum of k (x) v
__device__ float g_Kc[HEADS * HW * HW * D];             // 4 MB k integral (row, then 2D)
__device__ float g_Cat[(size_t)NTOK * INCDIM];          // 12.6 MB window-output concat

// ---------------- packed fp32x2 FMA (exact fp32, 2x issue density) -----------
__device__ __forceinline__ void ffma2(float2& d, float2 a, float2 b) {
    asm("fma.rn.f32x2 %0, %1, %2, %0;"
        : "+l"(*reinterpret_cast<unsigned long long*>(&d))
        : "l"(*reinterpret_cast<unsigned long long*>(&a)),
          "l"(*reinterpret_cast<unsigned long long*>(&b)));
}

__device__ __forceinline__ void cp_async16(uint32_t s, const float* g) {
    asm volatile("cp.async.cg.shared.global [%0], [%1], 16;" :: "r"(s), "l"(g));
}
__device__ __forceinline__ void cp_commit() {
    asm volatile("cp.async.commit_group;");
}
template <int N>
__device__ __forceinline__ void cp_wait() {
    asm volatile("cp.async.wait_group %0;" :: "n"(N));
}

// ---------------- Kernel 1: fused QKV GEMM + ELU epilogue --------------------
__global__ __launch_bounds__(128) void k_qkv(const float* __restrict__ x,
                                             const float* __restrict__ wq,
                                             const float* __restrict__ wk,
                                             const float* __restrict__ wv) {
    __shared__ float As[32 * 64];    // [kk][m]
    __shared__ float Bs[32 * 128];   // [kk][n]
    const int row0 = blockIdx.x * 64;
    const int col0g = blockIdx.y * 128;     // 0..767
    const int part = col0g >> 8;            // 0=q 1=k 2=v
    const int col0 = col0g & 255;
    const float* W = (part == 0) ? wq : (part == 1) ? wk : wv;
    const int tid = threadIdx.x;
    const int tx = tid & 15, ty = tid >> 4;

    float4 pa[4];
    float4 pb[8];
#pragma unroll
    for (int i = 0; i < 4; i++) {
        int l = tid + i * 128;
        int m = l & 63, kq = l >> 6;
        pa[i] = *(const float4*)&x[(size_t)(row0 + m) * DIMX + kq * 4];
    }
#pragma unroll
    for (int i = 0; i < 8; i++) {
        int l = tid + i * 128;
        int n4 = l & 31, kk = l >> 5;
        pb[i] = *(const float4*)&W[(size_t)kk * DIMX + col0 + n4 * 4];
    }

    float2 acc[8][4] = {};
    for (int k0 = 0; k0 < DIMX; k0 += 32) {
#pragma unroll
        for (int i = 0; i < 4; i++) {
            int l = tid + i * 128;
            int m = l & 63, kq = l >> 6;
            As[(kq * 4 + 0) * 64 + m] = pa[i].x;
            As[(kq * 4 + 1) * 64 + m] = pa[i].y;
            As[(kq * 4 + 2) * 64 + m] = pa[i].z;
            As[(kq * 4 + 3) * 64 + m] = pa[i].w;
        }
#pragma unroll
        for (int i = 0; i < 8; i++) {
            int l = tid + i * 128;
            int n4 = l & 31, kk = l >> 5;
            *(float4*)&Bs[kk * 128 + n4 * 4] = pb[i];
        }
        __syncthreads();
        if (k0 + 32 < DIMX) {
#pragma unroll
            for (int i = 0; i < 4; i++) {
                int l = tid + i * 128;
                int m = l & 63, kq = l >> 6;
                pa[i] = *(const float4*)&x[(size_t)(row0 + m) * DIMX + k0 + 32 + kq * 4];
            }
#pragma unroll
            for (int i = 0; i < 8; i++) {
                int l = tid + i * 128;
                int n4 = l & 31, kk = l >> 5;
                pb[i] = *(const float4*)&W[(size_t)(k0 + 32 + kk) * DIMX + col0 + n4 * 4];
            }
        }
#pragma unroll
        for (int kk = 0; kk < 32; kk++) {
            float4 a0 = *(float4*)&As[kk * 64 + ty * 8];
            float4 a1 = *(float4*)&As[kk * 64 + ty * 8 + 4];
            float av[8] = {a0.x, a0.y, a0.z, a0.w, a1.x, a1.y, a1.z, a1.w};
            float2 bv[4];
            bv[0] = *(float2*)&Bs[kk * 128 + tx * 8 + 0];
            bv[1] = *(float2*)&Bs[kk * 128 + tx * 8 + 2];
            bv[2] = *(float2*)&Bs[kk * 128 + tx * 8 + 4];
            bv[3] = *(float2*)&Bs[kk * 128 + tx * 8 + 6];
#pragma unroll
            for (int i = 0; i < 8; i++) {
                float2 a2 = {av[i], av[i]};
#pragma unroll
                for (int j = 0; j < 4; j++) ffma2(acc[i][j], a2, bv[j]);
            }
        }
        __syncthreads();
    }

    float* dst = (part == 0) ? g_Q : (part == 1) ? g_K : g_V;
    const int ccb = col0 + tx * 8;           // 8 consecutive cols, within one head
    const int h = ccb >> 5, e0 = ccb & 31;
#pragma unroll
    for (int i = 0; i < 8; i++) {
        int n = row0 + ty * 8 + i;
        float v[8] = {acc[i][0].x, acc[i][0].y, acc[i][1].x, acc[i][1].y,
                      acc[i][2].x, acc[i][2].y, acc[i][3].x, acc[i][3].y};
        if (part < 2) {
#pragma unroll
            for (int j = 0; j < 8; j++)
                v[j] = (v[j] > 0.f) ? (v[j] + 1.000001f) : (expf(v[j]) + 1e-6f);
        }
        float* p = &dst[((size_t)(h * NTOK + n)) * D + e0];
        *(float4*)p = make_float4(v[0], v[1], v[2], v[3]);
        *(float4*)(p + 4) = make_float4(v[4], v[5], v[6], v[7]);
    }
}

// ---------------- Kernel 2: row-direction cumsums ----------------------------
__global__ __launch_bounds__(256) void k_integral() {
    const int j = blockIdx.x;
    const int h = blockIdx.y;
    __shared__ float ksh[HW * D];
    __shared__ float vsh[HW * D];
    const int tid = threadIdx.x;
#pragma unroll
    for (int r = 0; r < 8; r++) {
        int l = tid + r * 256;
        int i = l >> 5, a = l & 31;
        size_t gi = ((size_t)(h * NTOK + i * HW + j)) * D + a;
        ksh[l] = g_K[gi];
        vsh[l] = g_V[gi];
    }
    __syncthreads();
    const int a = tid >> 3;
    const int b = (tid & 7) * 4;
    float4 acc = make_float4(0.f, 0.f, 0.f, 0.f);
    float kacc = 0.f;
    for (int i = 0; i < HW; i++) {
        float kv = ksh[i * D + a];
        float4 vv = *(const float4*)&vsh[i * D + b];
        acc.x += kv * vv.x; acc.y += kv * vv.y; acc.z += kv * vv.z; acc.w += kv * vv.w;
        *(float4*)&g_U[(((size_t)(h * HW + i)) * HW + j) * (D * D) + tid * 4] = acc;
        if (tid < 32) {
            kacc += ksh[i * D + tid];
            g_Kc[((h * HW + i) * HW + j) * D + tid] = kacc;
        }
    }
}

// ---------------- Kernel 3: column scan of g_Kc -> full 2D k integral --------
__global__ __launch_bounds__(256) void k_scan() {
    const int i = blockIdx.x;
    const int h = blockIdx.y;
    __shared__ float s[HW * D];
    float* row = g_Kc + (size_t)(h * HW + i) * HW * D;
    const int tid = threadIdx.x;
#pragma unroll
    for (int r = 0; r < 8; r++) s[tid + r * 256] = row[tid + r * 256];
    __syncthreads();
    if (tid < 32) {
        float acc = 0.f;
        for (int j = 0; j < HW; j++) {
            acc += s[j * D + tid];
            s[j * D + tid] = acc;
        }
    }
    __syncthreads();
#pragma unroll
    for (int r = 0; r < 8; r++) row[tid + r * 256] = s[tid + r * 256];
}

// ---------------- Kernel 4: windowed linear attention sweep ------------------
// block = (ii, window, head). cp.async 6-stage U ring (self-consumed 16B per
// thread -> no data barrier). Prefix published to an 8-slot ring; ONE barrier
// per 4-column batch; batch events round-robined across all 8 warps.
__global__ __launch_bounds__(256) void k_attn() {
    extern __shared__ float smem[];
    float* qsh   = smem;                 // 2048
    float* numsh = smem + 2048;          // 2048
    float* Msh   = smem + 4096;          // 8 * 1024
    float* Uring = smem + 12288;         // NSTAGE * 2048
    float* densh = smem + 12288 + NSTAGE * 2048;  // 64

    const int ii = blockIdx.x;
    const int win = blockIdx.y;
    const int h = blockIdx.z;
    const int r = (win == 0) ? 32 : (win == 1) ? 16 : 8;

    const int tid = threadIdx.x;
    const int warp = tid >> 5, lane = tid & 31;

#pragma unroll
    for (int rr = 0; rr < 8; rr++) {
        int l = tid + rr * 256;
        qsh[l] = g_Q[((size_t)(h * NTOK + ii * HW)) * D + l];
        numsh[l] = 0.f;
    }

    const int x2 = min(ii + r, HW - 1);
    const int xl = ii - r - 1;
    const bool hasl = (xl >= 0);
    const float* Uh = g_U + ((size_t)(h * HW + x2)) * HW * (D * D) + tid * 4;
    const float* Ul = g_U + ((size_t)(h * HW + max(xl, 0))) * HW * (D * D) + tid * 4;

    uint32_t urbase = (uint32_t)__cvta_generic_to_shared(Uring) + tid * 16;
    // warmup: stages for j = 0..NSTAGE-1, one commit group per column
#pragma unroll
    for (int s = 0; s < NSTAGE; s++) {
        cp_async16(urbase + s * 8192, Uh + (size_t)s * (D * D));
        if (hasl) cp_async16(urbase + s * 8192 + 4096, Ul + (size_t)s * (D * D));
        cp_commit();
    }

    float4 mreg = make_float4(0.f, 0.f, 0.f, 0.f);
    __syncthreads();   // init writes (numsh/qsh) visible

    int base = 0;
    for (int j0 = 0; j0 < HW; j0 += MB) {
        // ---- publish phase: consume MB stages, update prefix, publish slots
#pragma unroll
        for (int u = 0; u < MB; u++) {
            const int j = j0 + u;
            cp_wait<NSTAGE - 1>();   // group for column j complete
            const int st = j % NSTAGE;
            float4 dd = *(float4*)&Uring[st * 2048 + tid * 4];
            if (hasl) {
                float4 dl = *(float4*)&Uring[st * 2048 + 1024 + tid * 4];
                dd.x -= dl.x; dd.y -= dl.y; dd.z -= dl.z; dd.w -= dl.w;
            }
            mreg.x += dd.x; mreg.y += dd.y; mreg.z += dd.z; mreg.w += dd.w;
            *(float4*)&Msh[((j & 7) << 10) + tid * 4] = mreg;
            // refill same stage for column j + NSTAGE
            if (j + NSTAGE < HW) {
                cp_async16(urbase + st * 8192, Uh + (size_t)(j + NSTAGE) * (D * D));
                if (hasl) cp_async16(urbase + st * 8192 + 4096, Ul + (size_t)(j + NSTAGE) * (D * D));
            }
            cp_commit();   // always commit (keeps group indexing aligned)
        }
        __syncthreads();   // slots j0..j0+3 visible; prior batch events done

        // ---- event phase: all warps share this batch's events
#pragma unroll
        for (int u = 0; u < MB; u++) {
            const int j = j0 + u;
            const int nplus = (j == HW - 1) ? (r + 1) : ((j >= r) ? 1 : 0);
            const int jjp0  = (j == HW - 1) ? (HW - 1 - r) : (j - r);
            const int hasminus = (j + r + 1 <= HW - 1) ? 1 : 0;
            const int nev = nplus + hasminus;
            const float* M = Msh + ((j & 7) << 10);
            int e0w = warp - base; if (e0w < 0) e0w += 8;
            for (int e = e0w; e < nev; e += 8) {
                int jj; float sgn;
                if (e < nplus) { jj = jjp0 + e; sgn = 1.f; }
                else           { jj = j + r + 1; sgn = -1.f; }
                const float* qrow = &qsh[jj * D];
                float r0 = 0.f, r1 = 0.f;
#pragma unroll
                for (int a = 0; a < 32; a += 8) {
                    float4 q0 = *(const float4*)&qrow[a];
                    float4 q1 = *(const float4*)&qrow[a + 4];
                    r0 += q0.x * M[(a + 0) * 32 + lane] + q0.y * M[(a + 1) * 32 + lane]
                        + q0.z * M[(a + 2) * 32 + lane] + q0.w * M[(a + 3) * 32 + lane];
                    r1 += q1.x * M[(a + 4) * 32 + lane] + q1.y * M[(a + 5) * 32 + lane]
                        + q1.z * M[(a + 6) * 32 + lane] + q1.w * M[(a + 7) * 32 + lane];
                }
                numsh[jj * D + lane] += sgn * (r0 + r1);
            }
            base += nev; base &= 7;
        }
    }
    __syncthreads();

    // denominator: 4-corner reads of full 2D k integral (g_Kc after k_scan)
    const float* S2 = g_Kc + (size_t)(h * HW + x2) * HW * D;
    const float* Sl = g_Kc + (size_t)(h * HW + max(xl, 0)) * HW * D;
    for (int jj = warp; jj < HW; jj += 8) {
        const int y2 = min(jj + r, HW - 1);
        const int yl = jj - r - 1;
        float v = S2[y2 * D + lane];
        if (hasl) v -= Sl[y2 * D + lane];
        if (yl >= 0) {
            v -= S2[yl * D + lane];
            if (hasl) v += Sl[yl * D + lane];
        }
        float p = qsh[jj * D + lane] * v;
#pragma unroll
        for (int off = 16; off; off >>= 1) p += __shfl_xor_sync(0xffffffffu, p, off);
        if (lane == 0) densh[jj] = p;
    }
    __syncthreads();

    // write o = num/den to g_Cat
#pragma unroll
    for (int rr = 0; rr < 8; rr++) {
        int l = tid + rr * 256;
        int jj = l >> 5, e = l & 31;
        float o = numsh[l] / (densh[jj] + 1e-6f);
        g_Cat[(size_t)(ii * HW + jj) * INCDIM + win * DIMX + h * D + e] = o;
    }
}

// ---------------- Kernel 5: output GEMM + bias -------------------------------
__global__ __launch_bounds__(256) void k_out(const float* __restrict__ wo,
                                             const float* __restrict__ bo,
                                             float* __restrict__ out) {
    __shared__ float As[32 * 64];    // [kk][m]
    __shared__ float Bs[32 * 128];   // [kk][n]
    const int row0 = blockIdx.x * 64;
    const int col0 = blockIdx.y * 128;
    const int tid = threadIdx.x;
    const int tx = tid & 15, ty = tid >> 4;

    float4 pa[2], pb[4];
#pragma unroll
    for (int i = 0; i < 2; i++) {
        int l = tid + i * 256;
        int m = l & 63, kq = l >> 6;
        pa[i] = *(const float4*)&g_Cat[(size_t)(row0 + m) * INCDIM + kq * 4];
    }
#pragma unroll
    for (int i = 0; i < 4; i++) {
        int l = tid + i * 256;
        int n4 = l & 31, kk = l >> 5;
        pb[i] = *(const float4*)&wo[(size_t)kk * DIMX + col0 + n4 * 4];
    }

    float2 acc[4][4] = {};
    for (int k0 = 0; k0 < INCDIM; k0 += 32) {
#pragma unroll
        for (int i = 0; i < 2; i++) {
            int l = tid + i * 256;
            int m = l & 63, kq = l >> 6;
            As[(kq * 4 + 0) * 64 + m] = pa[i].x;
            As[(kq * 4 + 1) * 64 + m] = pa[i].y;
            As[(kq * 4 + 2) * 64 + m] = pa[i].z;
            As[(kq * 4 + 3) * 64 + m] = pa[i].w;
        }
#pragma unroll
        for (int i = 0; i < 4; i++) {
            int l = tid + i * 256;
            int n4 = l & 31, kk = l >> 5;
            *(float4*)&Bs[kk * 128 + n4 * 4] = pb[i];
        }
        __syncthreads();
        if (k0 + 32 < INCDIM) {
#pragma unroll
            for (int i = 0; i < 2; i++) {
                int l = tid + i * 256;
                int m = l & 63, kq = l >> 6;
                pa[i] = *(const float4*)&g_Cat[(size_t)(row0 + m) * INCDIM + k0 + 32 + kq * 4];
            }
#pragma unroll
            for (int i = 0; i < 4; i++) {
                int l = tid + i * 256;
                int n4 = l & 31, kk = l >> 5;
                pb[i] = *(const float4*)&wo[(size_t)(k0 + 32 + kk) * DIMX + col0 + n4 * 4];
            }
        }
#pragma unroll
        for (int kk = 0; kk < 32; kk++) {
            float4 av = *(float4*)&As[kk * 64 + ty * 4];
            float4 b0 = *(float4*)&Bs[kk * 128 + tx * 8];
            float4 b1 = *(float4*)&Bs[kk * 128 + tx * 8 + 4];
            float a[4] = {av.x, av.y, av.z, av.w};
            float2 bv[4] = {{b0.x, b0.y}, {b0.z, b0.w}, {b1.x, b1.y}, {b1.z, b1.w}};
#pragma unroll
            for (int i = 0; i < 4; i++) {
                float2 a2 = {a[i], a[i]};
#pragma unroll
                for (int j = 0; j < 4; j++) ffma2(acc[i][j], a2, bv[j]);
            }
        }
        __syncthreads();
    }
#pragma unroll
    for (int i = 0; i < 4; i++) {
        int n = row0 + ty * 4 + i;
        int cb = col0 + tx * 8;
#pragma unroll
        for (int j = 0; j < 4; j++) {
            out[(size_t)n * DIMX + cb + j * 2]     = acc[i][j].x + bo[cb + j * 2];
            out[(size_t)n * DIMX + cb + j * 2 + 1] = acc[i][j].y + bo[cb + j * 2 + 1];
        }
    }
}

// ---------------- launch -----------------------------------------------------
#define ATTN_SMEM ((12288 + NSTAGE * 2048 + 64) * 4)

extern "C" void kernel_launch(void* const* d_in, const int* in_sizes, int n_in,
                              void* d_out, int out_size) {
    const float* x  = (const float*)d_in[0];
    const float* wq = (const float*)d_in[1];
    const float* wk = (const float*)d_in[2];
    const float* wv = (const float*)d_in[3];
    const float* wo = (const float*)d_in[4];
    const float* bo = (const float*)d_in[5];
    float* out = (float*)d_out;

    cudaFuncSetAttribute(k_attn, cudaFuncAttributeMaxDynamicSharedMemorySize, ATTN_SMEM);

    k_qkv<<<dim3(NTOK / 64, INCDIM / 128), 128>>>(x, wq, wk, wv);
    k_integral<<<dim3(HW, HEADS), 256>>>();
    k_scan<<<dim3(HW, HEADS), 256>>>();
    k_attn<<<dim3(HW, 3, HEADS), 256, ATTN_SMEM>>>();
    k_out<<<dim3(NTOK / 64, DIMX / 128), 256>>>(wo, bo, out);
}

// round 9
// speedup vs baseline: 1.1725x; 1.1725x over previous
#include <cuda_runtime.h>
#include <stdint.h>
#include <math.h>

#define HEADS 8
#define HW 64
#define D 32
#define NTOK 4096
#define DIMX 256
#define INCDIM 768
#define MB 4

// ---------------- scratch (static device globals; no allocation) -------------
__device__ float g_Q[HEADS * NTOK * D];                 // 4 MB
__device__ float g_K[HEADS * NTOK * D];                 // 4 MB
__device__ float g_V[HEADS * NTOK * D];                 // 4 MB
__device__ float g_U[(size_t)HEADS * HW * HW * D * D];  // 134 MB row-cumsum of k (x) v
__device__ float g_Kc[HEADS * HW * HW * D];             // 4 MB k integral (row, then 2D)
__device__ float g_Cat[(size_t)NTOK * INCDIM];          // 12.6 MB window-output concat

// ---------------- packed fp32x2 FMA (exact fp32, 2x issue density) -----------
__device__ __forceinline__ void ffma2(float2& d, float2 a, float2 b) {
    asm("fma.rn.f32x2 %0, %1, %2, %0;"
        : "+l"(*reinterpret_cast<unsigned long long*>(&d))
        : "l"(*reinterpret_cast<unsigned long long*>(&a)),
          "l"(*reinterpret_cast<unsigned long long*>(&b)));
}

// ---------------- Kernel 1: fused QKV GEMM + ELU epilogue --------------------
__global__ __launch_bounds__(128) void k_qkv(const float* __restrict__ x,
                                             const float* __restrict__ wq,
                                             const float* __restrict__ wk,
                                             const float* __restrict__ wv) {
    __shared__ float As[32 * 64];    // [kk][m]
    __shared__ float Bs[32 * 128];   // [kk][n]
    const int row0 = blockIdx.x * 64;
    const int col0g = blockIdx.y * 128;     // 0..767
    const int part = col0g >> 8;            // 0=q 1=k 2=v
    const int col0 = col0g & 255;
    const float* W = (part == 0) ? wq : (part == 1) ? wk : wv;
    const int tid = threadIdx.x;
    const int tx = tid & 15, ty = tid >> 4;

    float4 pa[4];
    float4 pb[8];
#pragma unroll
    for (int i = 0; i < 4; i++) {
        int l = tid + i * 128;
        int m = l & 63, kq = l >> 6;
        pa[i] = *(const float4*)&x[(size_t)(row0 + m) * DIMX + kq * 4];
    }
#pragma unroll
    for (int i = 0; i < 8; i++) {
        int l = tid + i * 128;
        int n4 = l & 31, kk = l >> 5;
        pb[i] = *(const float4*)&W[(size_t)kk * DIMX + col0 + n4 * 4];
    }

    float2 acc[8][4] = {};
    for (int k0 = 0; k0 < DIMX; k0 += 32) {
#pragma unroll
        for (int i = 0; i < 4; i++) {
            int l = tid + i * 128;
            int m = l & 63, kq = l >> 6;
            As[(kq * 4 + 0) * 64 + m] = pa[i].x;
            As[(kq * 4 + 1) * 64 + m] = pa[i].y;
            As[(kq * 4 + 2) * 64 + m] = pa[i].z;
            As[(kq * 4 + 3) * 64 + m] = pa[i].w;
        }
#pragma unroll
        for (int i = 0; i < 8; i++) {
            int l = tid + i * 128;
            int n4 = l & 31, kk = l >> 5;
            *(float4*)&Bs[kk * 128 + n4 * 4] = pb[i];
        }
        __syncthreads();
        if (k0 + 32 < DIMX) {
#pragma unroll
            for (int i = 0; i < 4; i++) {
                int l = tid + i * 128;
                int m = l & 63, kq = l >> 6;
                pa[i] = *(const float4*)&x[(size_t)(row0 + m) * DIMX + k0 + 32 + kq * 4];
            }
#pragma unroll
            for (int i = 0; i < 8; i++) {
                int l = tid + i * 128;
                int n4 = l & 31, kk = l >> 5;
                pb[i] = *(const float4*)&W[(size_t)(k0 + 32 + kk) * DIMX + col0 + n4 * 4];
            }
        }
#pragma unroll
        for (int kk = 0; kk < 32; kk++) {
            float4 a0 = *(float4*)&As[kk * 64 + ty * 8];
            float4 a1 = *(float4*)&As[kk * 64 + ty * 8 + 4];
            float av[8] = {a0.x, a0.y, a0.z, a0.w, a1.x, a1.y, a1.z, a1.w};
            float2 bv[4];
            bv[0] = *(float2*)&Bs[kk * 128 + tx * 8 + 0];
            bv[1] = *(float2*)&Bs[kk * 128 + tx * 8 + 2];
            bv[2] = *(float2*)&Bs[kk * 128 + tx * 8 + 4];
            bv[3] = *(float2*)&Bs[kk * 128 + tx * 8 + 6];
#pragma unroll
            for (int i = 0; i < 8; i++) {
                float2 a2 = {av[i], av[i]};
#pragma unroll
                for (int j = 0; j < 4; j++) ffma2(acc[i][j], a2, bv[j]);
            }
        }
        __syncthreads();
    }

    float* dst = (part == 0) ? g_Q : (part == 1) ? g_K : g_V;
    const int ccb = col0 + tx * 8;           // 8 consecutive cols, within one head
    const int h = ccb >> 5, e0 = ccb & 31;
#pragma unroll
    for (int i = 0; i < 8; i++) {
        int n = row0 + ty * 8 + i;
        float v[8] = {acc[i][0].x, acc[i][0].y, acc[i][1].x, acc[i][1].y,
                      acc[i][2].x, acc[i][2].y, acc[i][3].x, acc[i][3].y};
        if (part < 2) {
#pragma unroll
            for (int j = 0; j < 8; j++)
                v[j] = (v[j] > 0.f) ? (v[j] + 1.000001f) : (expf(v[j]) + 1e-6f);
        }
        float* p = &dst[((size_t)(h * NTOK + n)) * D + e0];
        *(float4*)p = make_float4(v[0], v[1], v[2], v[3]);
        *(float4*)(p + 4) = make_float4(v[4], v[5], v[6], v[7]);
    }
}

// ---------------- Kernel 2: row-direction cumsums ----------------------------
__global__ __launch_bounds__(256) void k_integral() {
    const int j = blockIdx.x;
    const int h = blockIdx.y;
    __shared__ float ksh[HW * D];
    __shared__ float vsh[HW * D];
    const int tid = threadIdx.x;
#pragma unroll
    for (int r = 0; r < 8; r++) {
        int l = tid + r * 256;
        int i = l >> 5, a = l & 31;
        size_t gi = ((size_t)(h * NTOK + i * HW + j)) * D + a;
        ksh[l] = g_K[gi];
        vsh[l] = g_V[gi];
    }
    __syncthreads();
    const int a = tid >> 3;
    const int b = (tid & 7) * 4;
    float4 acc = make_float4(0.f, 0.f, 0.f, 0.f);
    float kacc = 0.f;
    for (int i = 0; i < HW; i++) {
        float kv = ksh[i * D + a];
        float4 vv = *(const float4*)&vsh[i * D + b];
        acc.x += kv * vv.x; acc.y += kv * vv.y; acc.z += kv * vv.z; acc.w += kv * vv.w;
        *(float4*)&g_U[(((size_t)(h * HW + i)) * HW + j) * (D * D) + tid * 4] = acc;
        if (tid < 32) {
            kacc += ksh[i * D + tid];
            g_Kc[((h * HW + i) * HW + j) * D + tid] = kacc;
        }
    }
}

// ---------------- Kernel 3: column scan of g_Kc -> full 2D k integral --------
__global__ __launch_bounds__(256) void k_scan() {
    const int i = blockIdx.x;
    const int h = blockIdx.y;
    __shared__ float s[HW * D];
    float* row = g_Kc + (size_t)(h * HW + i) * HW * D;
    const int tid = threadIdx.x;
#pragma unroll
    for (int r = 0; r < 8; r++) s[tid + r * 256] = row[tid + r * 256];
    __syncthreads();
    if (tid < 32) {
        float acc = 0.f;
        for (int j = 0; j < HW; j++) {
            acc += s[j * D + tid];
            s[j * D + tid] = acc;
        }
    }
    __syncthreads();
#pragma unroll
    for (int r = 0; r < 8; r++) row[tid + r * 256] = s[tid + r * 256];
}

// ---------------- Kernel 4: windowed linear attention sweep ------------------
// block = (ii, window, head). Register-staged LDG publish (no smem ring),
// 8-slot prefix ring, one barrier per 4-column batch, and PAIRED events:
// the two events of a column share one set of M loads (halves event LDS).
__global__ __launch_bounds__(256) void k_attn() {
    extern __shared__ float smem[];
    float* qsh   = smem;                 // 2048 floats
    float* numsh = smem + 2048;          // 2048
    float* Msh   = smem + 4096;          // 8 * 1024
    float* densh = smem + 4096 + 8192;   // 64

    const int ii = blockIdx.x;
    const int win = blockIdx.y;
    const int h = blockIdx.z;
    const int r = (win == 0) ? 32 : (win == 1) ? 16 : 8;

    const int tid = threadIdx.x;
    const int warp = tid >> 5, lane = tid & 31;

#pragma unroll
    for (int rr = 0; rr < 8; rr++) {
        int l = tid + rr * 256;
        qsh[l] = g_Q[((size_t)(h * NTOK + ii * HW)) * D + l];
        numsh[l] = 0.f;
    }

    const int x2 = min(ii + r, HW - 1);
    const int xl = ii - r - 1;
    const bool hasl = (xl >= 0);
    const float* Uh = g_U + ((size_t)(h * HW + x2)) * HW * (D * D) + tid * 4;
    const float* Ul = g_U + ((size_t)(h * HW + max(xl, 0))) * HW * (D * D) + tid * 4;

    // depth-4 register staging: stage u holds column j0+u; refilled to j+MB
    float4 sh[MB], sl[MB];
#pragma unroll
    for (int u = 0; u < MB; u++) {
        sh[u] = *(const float4*)&Uh[(size_t)u * (D * D)];
        if (hasl) sl[u] = *(const float4*)&Ul[(size_t)u * (D * D)];
    }
    float4 mreg = make_float4(0.f, 0.f, 0.f, 0.f);
    int rot = 0;
    __syncthreads();   // init writes (numsh/qsh) visible

    for (int j0 = 0; j0 < HW; j0 += MB) {
        // ---- publish phase: consume MB stages, update prefix, publish slots
#pragma unroll
        for (int u = 0; u < MB; u++) {
            const int j = j0 + u;
            float4 dd = sh[u];
            if (hasl) { dd.x -= sl[u].x; dd.y -= sl[u].y; dd.z -= sl[u].z; dd.w -= sl[u].w; }
            mreg.x += dd.x; mreg.y += dd.y; mreg.z += dd.z; mreg.w += dd.w;
            *(float4*)&Msh[((j & 7) << 10) + tid * 4] = mreg;
            if (j + MB < HW) {
                size_t off = (size_t)(j + MB) * (D * D);
                sh[u] = *(const float4*)&Uh[off];
                if (hasl) sl[u] = *(const float4*)&Ul[off];
            }
        }
        __syncthreads();   // slots j0..j0+3 visible; prior batch events done

        // ---- event phase: paired events share M loads; pairs over all warps
#pragma unroll
        for (int u = 0; u < MB; u++) {
            const int j = j0 + u;
            const int nplus = (j == HW - 1) ? (r + 1) : ((j >= r) ? 1 : 0);
            const int jjp0  = (j == HW - 1) ? (HW - 1 - r) : (j - r);
            const int hasminus = (j + r + 1 <= HW - 1) ? 1 : 0;
            const int nev = nplus + hasminus;
            const int npairs = (nev + 1) >> 1;
            const float* M = Msh + ((j & 7) << 10);
            int w0 = warp - rot; if (w0 < 0) w0 += 8;
            for (int p = w0; p < npairs; p += 8) {
                const int e0 = 2 * p, e1 = 2 * p + 1;
                const int jjA = (e0 < nplus) ? jjp0 + e0 : j + r + 1;
                const float sgnA = (e0 < nplus) ? 1.f : -1.f;
                const bool hasB = (e1 < nev);
                const int jjB = hasB ? ((e1 < nplus) ? jjp0 + e1 : j + r + 1) : jjA;
                const float sgnB = (e1 < nplus) ? 1.f : -1.f;
                const float* qA = &qsh[jjA * D];
                const float* qB = &qsh[jjB * D];
                float rA = 0.f, rB = 0.f;
#pragma unroll
                for (int a = 0; a < 32; a += 4) {
                    float4 qa = *(const float4*)&qA[a];
                    float4 qb = *(const float4*)&qB[a];
                    float m0 = M[(a + 0) * 32 + lane];
                    float m1 = M[(a + 1) * 32 + lane];
                    float m2 = M[(a + 2) * 32 + lane];
                    float m3 = M[(a + 3) * 32 + lane];
                    rA += qa.x * m0 + qa.y * m1 + qa.z * m2 + qa.w * m3;
                    rB += qb.x * m0 + qb.y * m1 + qb.z * m2 + qb.w * m3;
                }
                numsh[jjA * D + lane] += sgnA * rA;
                if (hasB) numsh[jjB * D + lane] += sgnB * rB;
            }
            rot += npairs; rot &= 7;
        }
    }
    __syncthreads();

    // denominator: 4-corner reads of full 2D k integral (g_Kc after k_scan)
    const float* S2 = g_Kc + (size_t)(h * HW + x2) * HW * D;
    const float* Sl = g_Kc + (size_t)(h * HW + max(xl, 0)) * HW * D;
    for (int jj = warp; jj < HW; jj += 8) {
        const int y2 = min(jj + r, HW - 1);
        const int yl = jj - r - 1;
        float v = S2[y2 * D + lane];
        if (hasl) v -= Sl[y2 * D + lane];
        if (yl >= 0) {
            v -= S2[yl * D + lane];
            if (hasl) v += Sl[yl * D + lane];
        }
        float p = qsh[jj * D + lane] * v;
#pragma unroll
        for (int off = 16; off; off >>= 1) p += __shfl_xor_sync(0xffffffffu, p, off);
        if (lane == 0) densh[jj] = p;
    }
    __syncthreads();

    // write o = num/den to g_Cat
#pragma unroll
    for (int rr = 0; rr < 8; rr++) {
        int l = tid + rr * 256;
        int jj = l >> 5, e = l & 31;
        float o = numsh[l] / (densh[jj] + 1e-6f);
        g_Cat[(size_t)(ii * HW + jj) * INCDIM + win * DIMX + h * D + e] = o;
    }
}

// ---------------- Kernel 5: output GEMM + bias -------------------------------
__global__ __launch_bounds__(256) void k_out(const float* __restrict__ wo,
                                             const float* __restrict__ bo,
                                             float* __restrict__ out) {
    __shared__ float As[32 * 64];    // [kk][m]
    __shared__ float Bs[32 * 128];   // [kk][n]
    const int row0 = blockIdx.x * 64;
    const int col0 = blockIdx.y * 128;
    const int tid = threadIdx.x;
    const int tx = tid & 15, ty = tid >> 4;

    float4 pa[2], pb[4];
#pragma unroll
    for (int i = 0; i < 2; i++) {
        int l = tid + i * 256;
        int m = l & 63, kq = l >> 6;
        pa[i] = *(const float4*)&g_Cat[(size_t)(row0 + m) * INCDIM + kq * 4];
    }
#pragma unroll
    for (int i = 0; i < 4; i++) {
        int l = tid + i * 256;
        int n4 = l & 31, kk = l >> 5;
        pb[i] = *(const float4*)&wo[(size_t)kk * DIMX + col0 + n4 * 4];
    }

    float2 acc[4][4] = {};
    for (int k0 = 0; k0 < INCDIM; k0 += 32) {
#pragma unroll
        for (int i = 0; i < 2; i++) {
            int l = tid + i * 256;
            int m = l & 63, kq = l >> 6;
            As[(kq * 4 + 0) * 64 + m] = pa[i].x;
            As[(kq * 4 + 1) * 64 + m] = pa[i].y;
            As[(kq * 4 + 2) * 64 + m] = pa[i].z;
            As[(kq * 4 + 3) * 64 + m] = pa[i].w;
        }
#pragma unroll
        for (int i = 0; i < 4; i++) {
            int l = tid + i * 256;
            int n4 = l & 31, kk = l >> 5;
            *(float4*)&Bs[kk * 128 + n4 * 4] = pb[i];
        }
        __syncthreads();
        if (k0 + 32 < INCDIM) {
#pragma unroll
            for (int i = 0; i < 2; i++) {
                int l = tid + i * 256;
                int m = l & 63, kq = l >> 6;
                pa[i] = *(const float4*)&g_Cat[(size_t)(row0 + m) * INCDIM + k0 + 32 + kq * 4];
            }
#pragma unroll
            for (int i = 0; i < 4; i++) {
                int l = tid + i * 256;
                int n4 = l & 31, kk = l >> 5;
                pb[i] = *(const float4*)&wo[(size_t)(k0 + 32 + kk) * DIMX + col0 + n4 * 4];
            }
        }
#pragma unroll
        for (int kk = 0; kk < 32; kk++) {
            float4 av = *(float4*)&As[kk * 64 + ty * 4];
            float4 b0 = *(float4*)&Bs[kk * 128 + tx * 8];
            float4 b1 = *(float4*)&Bs[kk * 128 + tx * 8 + 4];
            float a[4] = {av.x, av.y, av.z, av.w};
            float2 bv[4] = {{b0.x, b0.y}, {b0.z, b0.w}, {b1.x, b1.y}, {b1.z, b1.w}};
#pragma unroll
            for (int i = 0; i < 4; i++) {
                float2 a2 = {a[i], a[i]};
#pragma unroll
                for (int j = 0; j < 4; j++) ffma2(acc[i][j], a2, bv[j]);
            }
        }
        __syncthreads();
    }
#pragma unroll
    for (int i = 0; i < 4; i++) {
        int n = row0 + ty * 4 + i;
        int cb = col0 + tx * 8;
#pragma unroll
        for (int j = 0; j < 4; j++) {
            out[(size_t)n * DIMX + cb + j * 2]     = acc[i][j].x + bo[cb + j * 2];
            out[(size_t)n * DIMX + cb + j * 2 + 1] = acc[i][j].y + bo[cb + j * 2 + 1];
        }
    }
}

// ---------------- launch -----------------------------------------------------
#define ATTN_SMEM ((2048 + 2048 + 8192 + 64) * 4)

extern "C" void kernel_launch(void* const* d_in, const int* in_sizes, int n_in,
                              void* d_out, int out_size) {
    const float* x  = (const float*)d_in[0];
    const float* wq = (const float*)d_in[1];
    const float* wk = (const float*)d_in[2];
    const float* wv = (const float*)d_in[3];
    const float* wo = (const float*)d_in[4];
    const float* bo = (const float*)d_in[5];
    float* out = (float*)d_out;

    cudaFuncSetAttribute(k_attn, cudaFuncAttributeMaxDynamicSharedMemorySize, ATTN_SMEM);

    k_qkv<<<dim3(NTOK / 64, INCDIM / 128), 128>>>(x, wq, wk, wv);
    k_integral<<<dim3(HW, HEADS), 256>>>();
    k_scan<<<dim3(HW, HEADS), 256>>>();
    k_attn<<<dim3(HW, 3, HEADS), 256, ATTN_SMEM>>>();
    k_out<<<dim3(NTOK / 64, DIMX / 128), 256>>>(wo, bo, out);
}

// round 10
// speedup vs baseline: 1.2118x; 1.0335x over previous
#include <cuda_runtime.h>
#include <cuda_bf16.h>
#include <stdint.h>
#include <math.h>

#define HEADS 8
#define HW 64
#define D 32
#define NTOK 4096
#define DIMX 256
#define INCDIM 768
#define MB 4

// ---------------- scratch (static device globals; no allocation) -------------
__device__ float g_Q[HEADS * NTOK * D];                 // 4 MB
__device__ float g_K[HEADS * NTOK * D];                 // 4 MB
__device__ float g_V[HEADS * NTOK * D];                 // 4 MB
__device__ float g_U[(size_t)HEADS * HW * HW * D * D];  // 134 MB row-cumsum of k (x) v
__device__ float g_Kc[HEADS * HW * HW * D];             // 4 MB k integral (row, then 2D)
__device__ float g_Cat[(size_t)NTOK * INCDIM];          // 12.6 MB window-output concat

// split-bf16 operands (hi + lo decomposition of fp32)
__device__ __nv_bfloat16 g_xh[NTOK * DIMX], g_xl[NTOK * DIMX];         // x rows [n][k]
__device__ __nv_bfloat16 g_wh[INCDIM * DIMX], g_wl[INCDIM * DIMX];     // [n][k] = W^T (qkv)
__device__ __nv_bfloat16 g_woh[DIMX * INCDIM], g_wol[DIMX * INCDIM];   // [n][k] = wo^T
__device__ __nv_bfloat16 g_ch[(size_t)NTOK * INCDIM], g_cl[(size_t)NTOK * INCDIM]; // Cat [n][k]

// ---------------- mma helpers ------------------------------------------------
__device__ __forceinline__ void mma_bf16(float4& d, uint32_t a0, uint32_t a1,
                                         uint32_t a2, uint32_t a3,
                                         uint32_t b0, uint32_t b1) {
    asm volatile(
        "mma.sync.aligned.m16n8k16.row.col.f32.bf16.bf16.f32 "
        "{%0,%1,%2,%3}, {%4,%5,%6,%7}, {%8,%9}, {%0,%1,%2,%3};"
        : "+f"(d.x), "+f"(d.y), "+f"(d.z), "+f"(d.w)
        : "r"(a0), "r"(a1), "r"(a2), "r"(a3), "r"(b0), "r"(b1));
}

__device__ __forceinline__ void ldm4(uint32_t& r0, uint32_t& r1, uint32_t& r2,
                                     uint32_t& r3, const __nv_bfloat16* p) {
    uint32_t addr = (uint32_t)__cvta_generic_to_shared(p);
    asm volatile("ldmatrix.sync.aligned.m8n8.x4.shared.b16 {%0,%1,%2,%3}, [%4];"
                 : "=r"(r0), "=r"(r1), "=r"(r2), "=r"(r3) : "r"(addr));
}

__device__ __forceinline__ void split2(float v, __nv_bfloat16& h, __nv_bfloat16& l) {
    h = __float2bfloat16(v);
    l = __float2bfloat16(v - __bfloat162float(h));
}

// ---------------- split kernels ----------------------------------------------
__global__ __launch_bounds__(256) void k_split_x(const float* __restrict__ x) {
    int i = blockIdx.x * 256 + threadIdx.x;        // float4 index
    float4 v = ((const float4*)x)[i];
    int o = i * 4;
    split2(v.x, g_xh[o + 0], g_xl[o + 0]);
    split2(v.y, g_xh[o + 1], g_xl[o + 1]);
    split2(v.z, g_xh[o + 2], g_xl[o + 2]);
    split2(v.w, g_xh[o + 3], g_xl[o + 3]);
}

__global__ __launch_bounds__(256) void k_split_w(const float* __restrict__ wq,
                                                 const float* __restrict__ wk,
                                                 const float* __restrict__ wv) {
    int o = blockIdx.x * 256 + threadIdx.x;        // o = n*256 + k, n in [0,768)
    int n = o >> 8, k = o & 255;
    const float* W = (n < 256) ? wq : (n < 512) ? wk : wv;
    float v = W[(k << 8) + (n & 255)];
    split2(v, g_wh[o], g_wl[o]);
}

__global__ __launch_bounds__(256) void k_split_wo(const float* __restrict__ wo) {
    int o = blockIdx.x * 256 + threadIdx.x;        // o = n*768 + k, n in [0,256)
    int n = o / INCDIM, k = o - n * INCDIM;
    float v = wo[k * DIMX + n];
    split2(v, g_woh[o], g_wol[o]);
}

__global__ __launch_bounds__(256) void k_split_cat() {
    int i = blockIdx.x * 256 + threadIdx.x;        // float4 index
    float4 v = ((const float4*)g_Cat)[i];
    size_t o = (size_t)i * 4;
    split2(v.x, g_ch[o + 0], g_cl[o + 0]);
    split2(v.y, g_ch[o + 1], g_cl[o + 1]);
    split2(v.z, g_ch[o + 2], g_cl[o + 2]);
    split2(v.w, g_ch[o + 3], g_cl[o + 3]);
}

// ---------------- Kernel 1: QKV GEMM (split-bf16 tensor core) + ELU ----------
// C[4096 x 768] = x @ [wq|wk|wv]; BM=128, BN=64, KC=32; 8 warps, 32x32/warp.
__global__ __launch_bounds__(256) void k_qkv_mma() {
    __shared__ __nv_bfloat16 Ah[128 * 32], Al[128 * 32];
    __shared__ __nv_bfloat16 Bh[64 * 32],  Bl[64 * 32];
    const int row0 = blockIdx.x * 128;
    const int col0g = blockIdx.y * 64;     // 0..767
    const int part = col0g >> 8;
    const int tid = threadIdx.x;
    const int warp = tid >> 5, lane = tid & 31;
    const int wm = warp & 3, wn = warp >> 2;
    const int group = lane >> 2, tg = lane & 3;
    const int lr = lane & 15, lc = lane >> 4;

    float4 acc[2][4];
#pragma unroll
    for (int t = 0; t < 2; t++)
#pragma unroll
        for (int nt = 0; nt < 4; nt++) acc[t][nt] = make_float4(0.f, 0.f, 0.f, 0.f);

    for (int k0 = 0; k0 < DIMX; k0 += 32) {
        {   // A: 128x32 hi+lo
            int m = tid >> 1, half = tid & 1;
            const uint4* sh = (const uint4*)&g_xh[((row0 + m) << 8) + k0 + half * 16];
            const uint4* sl = (const uint4*)&g_xl[((row0 + m) << 8) + k0 + half * 16];
            uint4* dh = (uint4*)&Ah[m * 32 + half * 16];
            uint4* dl = (uint4*)&Al[m * 32 + half * 16];
            dh[0] = sh[0]; dh[1] = sh[1];
            dl[0] = sl[0]; dl[1] = sl[1];
        }
        {   // B: 64x32 (first 128 threads hi, rest lo)
            int t2 = tid & 127;
            int n = t2 >> 1, half = t2 & 1;
            const __nv_bfloat16* gsrc = (tid < 128) ? g_wh : g_wl;
            __nv_bfloat16* dstb = (tid < 128) ? Bh : Bl;
            const uint4* s = (const uint4*)&gsrc[(col0g + n) * DIMX + k0 + half * 16];
            uint4* dp = (uint4*)&dstb[n * 32 + half * 16];
            dp[0] = s[0]; dp[1] = s[1];
        }
        __syncthreads();
#pragma unroll
        for (int kk = 0; kk < 32; kk += 16) {
            uint32_t ah[2][4], al[2][4];
#pragma unroll
            for (int t = 0; t < 2; t++) {
                const __nv_bfloat16* pa = &Ah[(wm * 32 + t * 16 + lr) * 32 + kk + lc * 8];
                const __nv_bfloat16* pl = &Al[(wm * 32 + t * 16 + lr) * 32 + kk + lc * 8];
                ldm4(ah[t][0], ah[t][1], ah[t][2], ah[t][3], pa);
                ldm4(al[t][0], al[t][1], al[t][2], al[t][3], pl);
            }
#pragma unroll
            for (int nt = 0; nt < 4; nt++) {
                int bi = (wn * 32 + nt * 8 + group) * 32 + kk + tg * 2;
                uint32_t bh0 = *(const uint32_t*)&Bh[bi];
                uint32_t bh1 = *(const uint32_t*)&Bh[bi + 8];
                uint32_t bl0 = *(const uint32_t*)&Bl[bi];
                uint32_t bl1 = *(const uint32_t*)&Bl[bi + 8];
#pragma unroll
                for (int t = 0; t < 2; t++) {
                    mma_bf16(acc[t][nt], ah[t][0], ah[t][1], ah[t][2], ah[t][3], bh0, bh1);
                    mma_bf16(acc[t][nt], ah[t][0], ah[t][1], ah[t][2], ah[t][3], bl0, bl1);
                    mma_bf16(acc[t][nt], al[t][0], al[t][1], al[t][2], al[t][3], bh0, bh1);
                }
            }
        }
        __syncthreads();
    }

    float* dst = (part == 0) ? g_Q : (part == 1) ? g_K : g_V;
    const int colbase = (col0g & 255) + wn * 32;
#pragma unroll
    for (int t = 0; t < 2; t++) {
#pragma unroll
        for (int nt = 0; nt < 4; nt++) {
            int row = row0 + wm * 32 + t * 16 + group;
            int colm = colbase + nt * 8 + tg * 2;
            int h = colm >> 5, e = colm & 31;
            float v0 = acc[t][nt].x, v1 = acc[t][nt].y;
            float v2 = acc[t][nt].z, v3 = acc[t][nt].w;
            if (part < 2) {
                v0 = (v0 > 0.f) ? (v0 + 1.000001f) : (expf(v0) + 1e-6f);
                v1 = (v1 > 0.f) ? (v1 + 1.000001f) : (expf(v1) + 1e-6f);
                v2 = (v2 > 0.f) ? (v2 + 1.000001f) : (expf(v2) + 1e-6f);
                v3 = (v3 > 0.f) ? (v3 + 1.000001f) : (expf(v3) + 1e-6f);
            }
            float* p0 = &dst[((size_t)(h * NTOK + row)) * D + e];
            p0[0] = v0; p0[1] = v1;
            float* p1 = &dst[((size_t)(h * NTOK + row + 8)) * D + e];
            p1[0] = v2; p1[1] = v3;
        }
    }
}

// ---------------- Kernel 2: row-direction cumsums ----------------------------
__global__ __launch_bounds__(256) void k_integral() {
    const int j = blockIdx.x;
    const int h = blockIdx.y;
    __shared__ float ksh[HW * D];
    __shared__ float vsh[HW * D];
    const int tid = threadIdx.x;
#pragma unroll
    for (int r = 0; r < 8; r++) {
        int l = tid + r * 256;
        int i = l >> 5, a = l & 31;
        size_t gi = ((size_t)(h * NTOK + i * HW + j)) * D + a;
        ksh[l] = g_K[gi];
        vsh[l] = g_V[gi];
    }
    __syncthreads();
    const int a = tid >> 3;
    const int b = (tid & 7) * 4;
    float4 acc = make_float4(0.f, 0.f, 0.f, 0.f);
    float kacc = 0.f;
    for (int i = 0; i < HW; i++) {
        float kv = ksh[i * D + a];
        float4 vv = *(const float4*)&vsh[i * D + b];
        acc.x += kv * vv.x; acc.y += kv * vv.y; acc.z += kv * vv.z; acc.w += kv * vv.w;
        *(float4*)&g_U[(((size_t)(h * HW + i)) * HW + j) * (D * D) + tid * 4] = acc;
        if (tid < 32) {
            kacc += ksh[i * D + tid];
            g_Kc[((h * HW + i) * HW + j) * D + tid] = kacc;
        }
    }
}

// ---------------- Kernel 3: column scan of g_Kc -> full 2D k integral --------
__global__ __launch_bounds__(256) void k_scan() {
    const int i = blockIdx.x;
    const int h = blockIdx.y;
    __shared__ float s[HW * D];
    float* row = g_Kc + (size_t)(h * HW + i) * HW * D;
    const int tid = threadIdx.x;
#pragma unroll
    for (int r = 0; r < 8; r++) s[tid + r * 256] = row[tid + r * 256];
    __syncthreads();
    if (tid < 32) {
        float acc = 0.f;
        for (int j = 0; j < HW; j++) {
            acc += s[j * D + tid];
            s[j * D + tid] = acc;
        }
    }
    __syncthreads();
#pragma unroll
    for (int r = 0; r < 8; r++) row[tid + r * 256] = s[tid + r * 256];
}

// ---------------- Kernel 4: windowed linear attention sweep (unchanged) ------
__global__ __launch_bounds__(256) void k_attn() {
    extern __shared__ float smem[];
    float* qsh   = smem;                 // 2048 floats
    float* numsh = smem + 2048;          // 2048
    float* Msh   = smem + 4096;          // 8 * 1024
    float* densh = smem + 4096 + 8192;   // 64

    const int ii = blockIdx.x;
    const int win = blockIdx.y;
    const int h = blockIdx.z;
    const int r = (win == 0) ? 32 : (win == 1) ? 16 : 8;

    const int tid = threadIdx.x;
    const int warp = tid >> 5, lane = tid & 31;

#pragma unroll
    for (int rr = 0; rr < 8; rr++) {
        int l = tid + rr * 256;
        qsh[l] = g_Q[((size_t)(h * NTOK + ii * HW)) * D + l];
        numsh[l] = 0.f;
    }

    const int x2 = min(ii + r, HW - 1);
    const int xl = ii - r - 1;
    const bool hasl = (xl >= 0);
    const float* Uh = g_U + ((size_t)(h * HW + x2)) * HW * (D * D) + tid * 4;
    const float* Ul = g_U + ((size_t)(h * HW + max(xl, 0))) * HW * (D * D) + tid * 4;

    float4 sh[MB], sl[MB];
#pragma unroll
    for (int u = 0; u < MB; u++) {
        sh[u] = *(const float4*)&Uh[(size_t)u * (D * D)];
        if (hasl) sl[u] = *(const float4*)&Ul[(size_t)u * (D * D)];
    }
    float4 mreg = make_float4(0.f, 0.f, 0.f, 0.f);
    int rot = 0;
    __syncthreads();

    for (int j0 = 0; j0 < HW; j0 += MB) {
#pragma unroll
        for (int u = 0; u < MB; u++) {
            const int j = j0 + u;
            float4 dd = sh[u];
            if (hasl) { dd.x -= sl[u].x; dd.y -= sl[u].y; dd.z -= sl[u].z; dd.w -= sl[u].w; }
            mreg.x += dd.x; mreg.y += dd.y; mreg.z += dd.z; mreg.w += dd.w;
            *(float4*)&Msh[((j & 7) << 10) + tid * 4] = mreg;
            if (j + MB < HW) {
                size_t off = (size_t)(j + MB) * (D * D);
                sh[u] = *(const float4*)&Uh[off];
                if (hasl) sl[u] = *(const float4*)&Ul[off];
            }
        }
        __syncthreads();

#pragma unroll
        for (int u = 0; u < MB; u++) {
            const int j = j0 + u;
            const int nplus = (j == HW - 1) ? (r + 1) : ((j >= r) ? 1 : 0);
            const int jjp0  = (j == HW - 1) ? (HW - 1 - r) : (j - r);
            const int hasminus = (j + r + 1 <= HW - 1) ? 1 : 0;
            const int nev = nplus + hasminus;
            const int npairs = (nev + 1) >> 1;
            const float* M = Msh + ((j & 7) << 10);
            int w0 = warp - rot; if (w0 < 0) w0 += 8;
            for (int p = w0; p < npairs; p += 8) {
                const int e0 = 2 * p, e1 = 2 * p + 1;
                const int jjA = (e0 < nplus) ? jjp0 + e0 : j + r + 1;
                const float sgnA = (e0 < nplus) ? 1.f : -1.f;
                const bool hasB = (e1 < nev);
                const int jjB = hasB ? ((e1 < nplus) ? jjp0 + e1 : j + r + 1) : jjA;
                const float sgnB = (e1 < nplus) ? 1.f : -1.f;
                const float* qA = &qsh[jjA * D];
                const float* qB = &qsh[jjB * D];
                float rA = 0.f, rB = 0.f;
#pragma unroll
                for (int a = 0; a < 32; a += 4) {
                    float4 qa = *(const float4*)&qA[a];
                    float4 qb = *(const float4*)&qB[a];
                    float m0 = M[(a + 0) * 32 + lane];
                    float m1 = M[(a + 1) * 32 + lane];
                    float m2 = M[(a + 2) * 32 + lane];
                    float m3 = M[(a + 3) * 32 + lane];
                    rA += qa.x * m0 + qa.y * m1 + qa.z * m2 + qa.w * m3;
                    rB += qb.x * m0 + qb.y * m1 + qb.z * m2 + qb.w * m3;
                }
                numsh[jjA * D + lane] += sgnA * rA;
                if (hasB) numsh[jjB * D + lane] += sgnB * rB;
            }
            rot += npairs; rot &= 7;
        }
    }
    __syncthreads();

    const float* S2 = g_Kc + (size_t)(h * HW + x2) * HW * D;
    const float* Sl = g_Kc + (size_t)(h * HW + max(xl, 0)) * HW * D;
    for (int jj = warp; jj < HW; jj += 8) {
        const int y2 = min(jj + r, HW - 1);
        const int yl = jj - r - 1;
        float v = S2[y2 * D + lane];
        if (hasl) v -= Sl[y2 * D + lane];
        if (yl >= 0) {
            v -= S2[yl * D + lane];
            if (hasl) v += Sl[yl * D + lane];
        }
        float p = qsh[jj * D + lane] * v;
#pragma unroll
        for (int off = 16; off; off >>= 1) p += __shfl_xor_sync(0xffffffffu, p, off);
        if (lane == 0) densh[jj] = p;
    }
    __syncthreads();

#pragma unroll
    for (int rr = 0; rr < 8; rr++) {
        int l = tid + rr * 256;
        int jj = l >> 5, e = l & 31;
        float o = numsh[l] / (densh[jj] + 1e-6f);
        g_Cat[(size_t)(ii * HW + jj) * INCDIM + win * DIMX + h * D + e] = o;
    }
}

// ---------------- Kernel 5: output GEMM (split-bf16 tensor core) + bias ------
// out[4096 x 256] = Cat @ wo + bo; BM=64, BN=64, KC=32; 8 warps, 32x16/warp.
__global__ __launch_bounds__(256) void k_out_mma(const float* __restrict__ bo,
                                                 float* __restrict__ out) {
    __shared__ __nv_bfloat16 Ah[64 * 32], Al[64 * 32];
    __shared__ __nv_bfloat16 Bh[64 * 32], Bl[64 * 32];
    const int row0 = blockIdx.x * 64;
    const int col0 = blockIdx.y * 64;
    const int tid = threadIdx.x;
    const int warp = tid >> 5, lane = tid & 31;
    const int wm = warp & 1, wn = warp >> 1;
    const int group = lane >> 2, tg = lane & 3;
    const int lr = lane & 15, lc = lane >> 4;

    float4 acc[2][2];
#pragma unroll
    for (int t = 0; t < 2; t++)
#pragma unroll
        for (int nt = 0; nt < 2; nt++) acc[t][nt] = make_float4(0.f, 0.f, 0.f, 0.f);

    const int m = tid >> 2, q = tid & 3;     // 64 rows x 4 quads of 8 bf16
    for (int k0 = 0; k0 < INCDIM; k0 += 32) {
        *(uint4*)&Ah[m * 32 + q * 8] = *(const uint4*)&g_ch[(size_t)(row0 + m) * INCDIM + k0 + q * 8];
        *(uint4*)&Al[m * 32 + q * 8] = *(const uint4*)&g_cl[(size_t)(row0 + m) * INCDIM + k0 + q * 8];
        *(uint4*)&Bh[m * 32 + q * 8] = *(const uint4*)&g_woh[(size_t)(col0 + m) * INCDIM + k0 + q * 8];
        *(uint4*)&Bl[m * 32 + q * 8] = *(const uint4*)&g_wol[(size_t)(col0 + m) * INCDIM + k0 + q * 8];
        __syncthreads();
#pragma unroll
        for (int kk = 0; kk < 32; kk += 16) {
            uint32_t ah[2][4], al[2][4];
#pragma unroll
            for (int t = 0; t < 2; t++) {
                const __nv_bfloat16* pa = &Ah[(wm * 32 + t * 16 + lr) * 32 + kk + lc * 8];
                const __nv_bfloat16* pl = &Al[(wm * 32 + t * 16 + lr) * 32 + kk + lc * 8];
                ldm4(ah[t][0], ah[t][1], ah[t][2], ah[t][3], pa);
                ldm4(al[t][0], al[t][1], al[t][2], al[t][3], pl);
            }
#pragma unroll
            for (int nt = 0; nt < 2; nt++) {
                int bi = (wn * 16 + nt * 8 + group) * 32 + kk + tg * 2;
                uint32_t bh0 = *(const uint32_t*)&Bh[bi];
                uint32_t bh1 = *(const uint32_t*)&Bh[bi + 8];
                uint32_t bl0 = *(const uint32_t*)&Bl[bi];
                uint32_t bl1 = *(const uint32_t*)&Bl[bi + 8];
#pragma unroll
                for (int t = 0; t < 2; t++) {
                    mma_bf16(acc[t][nt], ah[t][0], ah[t][1], ah[t][2], ah[t][3], bh0, bh1);
                    mma_bf16(acc[t][nt], ah[t][0], ah[t][1], ah[t][2], ah[t][3], bl0, bl1);
                    mma_bf16(acc[t][nt], al[t][0], al[t][1], al[t][2], al[t][3], bh0, bh1);
                }
            }
        }
        __syncthreads();
    }

#pragma unroll
    for (int t = 0; t < 2; t++) {
#pragma unroll
        for (int nt = 0; nt < 2; nt++) {
            int row = row0 + wm * 32 + t * 16 + group;
            int col = col0 + wn * 16 + nt * 8 + tg * 2;
            float b0 = bo[col], b1 = bo[col + 1];
            float* p0 = &out[(size_t)row * DIMX + col];
            p0[0] = acc[t][nt].x + b0;
            p0[1] = acc[t][nt].y + b1;
            float* p1 = &out[(size_t)(row + 8) * DIMX + col];
            p1[0] = acc[t][nt].z + b0;
            p1[1] = acc[t][nt].w + b1;
        }
    }
}

// ---------------- launch -----------------------------------------------------
#define ATTN_SMEM ((2048 + 2048 + 8192 + 64) * 4)

extern "C" void kernel_launch(void* const* d_in, const int* in_sizes, int n_in,
                              void* d_out, int out_size) {
    const float* x  = (const float*)d_in[0];
    const float* wq = (const float*)d_in[1];
    const float* wk = (const float*)d_in[2];
    const float* wv = (const float*)d_in[3];
    const float* wo = (const float*)d_in[4];
    const float* bo = (const float*)d_in[5];
    float* out = (float*)d_out;

    cudaFuncSetAttribute(k_attn, cudaFuncAttributeMaxDynamicSharedMemorySize, ATTN_SMEM);

    k_split_x<<<(NTOK * DIMX / 4) / 256, 256>>>(x);
    k_split_w<<<(INCDIM * DIMX) / 256, 256>>>(wq, wk, wv);
    k_split_wo<<<(DIMX * INCDIM) / 256, 256>>>(wo);
    k_qkv_mma<<<dim3(NTOK / 128, INCDIM / 64), 256>>>();
    k_integral<<<dim3(HW, HEADS), 256>>>();
    k_scan<<<dim3(HW, HEADS), 256>>>();
    k_attn<<<dim3(HW, 3, HEADS), 256, ATTN_SMEM>>>();
    k_split_cat<<<((NTOK * INCDIM) / 4) / 256, 256>>>();
    k_out_mma<<<dim3(NTOK / 64, DIMX / 64), 256>>>(bo, out);
}

// round 11
// speedup vs baseline: 1.4352x; 1.1844x over previous
#include <cuda_runtime.h>
#include <cuda_bf16.h>
#include <stdint.h>
#include <math.h>

#define HEADS 8
#define HW 64
#define D 32
#define NTOK 4096
#define DIMX 256
#define INCDIM 768
#define MB 4
#define LDS 40   // padded smem row stride (bf16) -> conflict-free ldmatrix

// ---------------- scratch (static device globals; no allocation) -------------
__device__ float g_Q[HEADS * NTOK * D];                 // 4 MB
__device__ float g_K[HEADS * NTOK * D];                 // 4 MB
__device__ float g_V[HEADS * NTOK * D];                 // 4 MB
__device__ float g_U[(size_t)HEADS * HW * HW * D * D];  // 134 MB row-cumsum of k (x) v
__device__ float g_Kc[HEADS * HW * HW * D];             // 4 MB k integral (row, then 2D)
__device__ float g_Cat[(size_t)NTOK * INCDIM];          // 12.6 MB window-output concat

// split-bf16 operands (hi + lo decomposition of fp32)
__device__ __nv_bfloat16 g_xh[NTOK * DIMX], g_xl[NTOK * DIMX];         // x rows [n][k]
__device__ __nv_bfloat16 g_wh[INCDIM * DIMX], g_wl[INCDIM * DIMX];     // [n][k] = W^T (qkv)
__device__ __nv_bfloat16 g_woh[DIMX * INCDIM], g_wol[DIMX * INCDIM];   // [n][k] = wo^T
__device__ __nv_bfloat16 g_ch[(size_t)NTOK * INCDIM], g_cl[(size_t)NTOK * INCDIM]; // Cat [n][k]

// ---------------- mma helpers ------------------------------------------------
__device__ __forceinline__ void mma_bf16(float4& d, uint32_t a0, uint32_t a1,
                                         uint32_t a2, uint32_t a3,
                                         uint32_t b0, uint32_t b1) {
    asm volatile(
        "mma.sync.aligned.m16n8k16.row.col.f32.bf16.bf16.f32 "
        "{%0,%1,%2,%3}, {%4,%5,%6,%7}, {%8,%9}, {%0,%1,%2,%3};"
        : "+f"(d.x), "+f"(d.y), "+f"(d.z), "+f"(d.w)
        : "r"(a0), "r"(a1), "r"(a2), "r"(a3), "r"(b0), "r"(b1));
}

__device__ __forceinline__ void ldm4(uint32_t& r0, uint32_t& r1, uint32_t& r2,
                                     uint32_t& r3, const __nv_bfloat16* p) {
    uint32_t addr = (uint32_t)__cvta_generic_to_shared(p);
    asm volatile("ldmatrix.sync.aligned.m8n8.x4.shared.b16 {%0,%1,%2,%3}, [%4];"
                 : "=r"(r0), "=r"(r1), "=r"(r2), "=r"(r3) : "r"(addr));
}

__device__ __forceinline__ void split2(float v, __nv_bfloat16& h, __nv_bfloat16& l) {
    h = __float2bfloat16(v);
    l = __float2bfloat16(v - __bfloat162float(h));
}

// ---------------- split kernels ----------------------------------------------
__global__ __launch_bounds__(256) void k_split_x(const float* __restrict__ x) {
    int i = blockIdx.x * 256 + threadIdx.x;        // float4 index
    float4 v = ((const float4*)x)[i];
    int o = i * 4;
    split2(v.x, g_xh[o + 0], g_xl[o + 0]);
    split2(v.y, g_xh[o + 1], g_xl[o + 1]);
    split2(v.z, g_xh[o + 2], g_xl[o + 2]);
    split2(v.w, g_xh[o + 3], g_xl[o + 3]);
}

__global__ __launch_bounds__(256) void k_split_w(const float* __restrict__ wq,
                                                 const float* __restrict__ wk,
                                                 const float* __restrict__ wv) {
    int o = blockIdx.x * 256 + threadIdx.x;        // o = n*256 + k, n in [0,768)
    int n = o >> 8, k = o & 255;
    const float* W = (n < 256) ? wq : (n < 512) ? wk : wv;
    float v = W[(k << 8) + (n & 255)];
    split2(v, g_wh[o], g_wl[o]);
}

__global__ __launch_bounds__(256) void k_split_wo(const float* __restrict__ wo) {
    int o = blockIdx.x * 256 + threadIdx.x;        // o = n*768 + k, n in [0,256)
    int n = o / INCDIM, k = o - n * INCDIM;
    float v = wo[k * DIMX + n];
    split2(v, g_woh[o], g_wol[o]);
}

__global__ __launch_bounds__(256) void k_split_cat() {
    int i = blockIdx.x * 256 + threadIdx.x;        // float4 index
    float4 v = ((const float4*)g_Cat)[i];
    size_t o = (size_t)i * 4;
    split2(v.x, g_ch[o + 0], g_cl[o + 0]);
    split2(v.y, g_ch[o + 1], g_cl[o + 1]);
    split2(v.z, g_ch[o + 2], g_cl[o + 2]);
    split2(v.w, g_ch[o + 3], g_cl[o + 3]);
}

// ---------------- Kernel 1: QKV GEMM (split-bf16 tensor core) + ELU ----------
// C[4096 x 768] = x @ [wq|wk|wv]; BM=128, BN=64, KC=32; 8 warps, 32x32/warp.
__global__ __launch_bounds__(256) void k_qkv_mma() {
    __shared__ __nv_bfloat16 Ah[128 * LDS], Al[128 * LDS];
    __shared__ __nv_bfloat16 Bh[64 * LDS],  Bl[64 * LDS];
    const int row0 = blockIdx.x * 128;
    const int col0g = blockIdx.y * 64;     // 0..767
    const int part = col0g >> 8;
    const int tid = threadIdx.x;
    const int warp = tid >> 5, lane = tid & 31;
    const int wm = warp & 3, wn = warp >> 2;
    const int group = lane >> 2, tg = lane & 3;
    const int lr = lane & 15, lc = lane >> 4;

    float4 acc[2][4];
#pragma unroll
    for (int t = 0; t < 2; t++)
#pragma unroll
        for (int nt = 0; nt < 4; nt++) acc[t][nt] = make_float4(0.f, 0.f, 0.f, 0.f);

    for (int k0 = 0; k0 < DIMX; k0 += 32) {
        {   // A: 128x32 hi+lo
            int m = tid >> 1, half = tid & 1;
            const uint4* sh = (const uint4*)&g_xh[((row0 + m) << 8) + k0 + half * 16];
            const uint4* sl = (const uint4*)&g_xl[((row0 + m) << 8) + k0 + half * 16];
            uint4* dh = (uint4*)&Ah[m * LDS + half * 16];
            uint4* dl = (uint4*)&Al[m * LDS + half * 16];
            dh[0] = sh[0]; dh[1] = sh[1];
            dl[0] = sl[0]; dl[1] = sl[1];
        }
        {   // B: 64x32 (first 128 threads hi, rest lo)
            int t2 = tid & 127;
            int n = t2 >> 1, half = t2 & 1;
            const __nv_bfloat16* gsrc = (tid < 128) ? g_wh : g_wl;
            __nv_bfloat16* dstb = (tid < 128) ? Bh : Bl;
            const uint4* s = (const uint4*)&gsrc[(col0g + n) * DIMX + k0 + half * 16];
            uint4* dp = (uint4*)&dstb[n * LDS + half * 16];
            dp[0] = s[0]; dp[1] = s[1];
        }
        __syncthreads();
#pragma unroll
        for (int kk = 0; kk < 32; kk += 16) {
            uint32_t ah[2][4], al[2][4];
#pragma unroll
            for (int t = 0; t < 2; t++) {
                const __nv_bfloat16* pa = &Ah[(wm * 32 + t * 16 + lr) * LDS + kk + lc * 8];
                const __nv_bfloat16* pl = &Al[(wm * 32 + t * 16 + lr) * LDS + kk + lc * 8];
                ldm4(ah[t][0], ah[t][1], ah[t][2], ah[t][3], pa);
                ldm4(al[t][0], al[t][1], al[t][2], al[t][3], pl);
            }
#pragma unroll
            for (int nt = 0; nt < 4; nt++) {
                int bi = (wn * 32 + nt * 8 + group) * LDS + kk + tg * 2;
                uint32_t bh0 = *(const uint32_t*)&Bh[bi];
                uint32_t bh1 = *(const uint32_t*)&Bh[bi + 8];
                uint32_t bl0 = *(const uint32_t*)&Bl[bi];
                uint32_t bl1 = *(const uint32_t*)&Bl[bi + 8];
#pragma unroll
                for (int t = 0; t < 2; t++) {
                    mma_bf16(acc[t][nt], ah[t][0], ah[t][1], ah[t][2], ah[t][3], bh0, bh1);
                    mma_bf16(acc[t][nt], ah[t][0], ah[t][1], ah[t][2], ah[t][3], bl0, bl1);
                    mma_bf16(acc[t][nt], al[t][0], al[t][1], al[t][2], al[t][3], bh0, bh1);
                }
            }
        }
        __syncthreads();
    }

    float* dst = (part == 0) ? g_Q : (part == 1) ? g_K : g_V;
    const int colbase = (col0g & 255) + wn * 32;
#pragma unroll
    for (int t = 0; t < 2; t++) {
#pragma unroll
        for (int nt = 0; nt < 4; nt++) {
            int row = row0 + wm * 32 + t * 16 + group;
            int colm = colbase + nt * 8 + tg * 2;
            int h = colm >> 5, e = colm & 31;
            float v0 = acc[t][nt].x, v1 = acc[t][nt].y;
            float v2 = acc[t][nt].z, v3 = acc[t][nt].w;
            if (part < 2) {
                v0 = (v0 > 0.f) ? (v0 + 1.000001f) : (expf(v0) + 1e-6f);
                v1 = (v1 > 0.f) ? (v1 + 1.000001f) : (expf(v1) + 1e-6f);
                v2 = (v2 > 0.f) ? (v2 + 1.000001f) : (expf(v2) + 1e-6f);
                v3 = (v3 > 0.f) ? (v3 + 1.000001f) : (expf(v3) + 1e-6f);
            }
            float* p0 = &dst[((size_t)(h * NTOK + row)) * D + e];
            p0[0] = v0; p0[1] = v1;
            float* p1 = &dst[((size_t)(h * NTOK + row + 8)) * D + e];
            p1[0] = v2; p1[1] = v3;
        }
    }
}

// ---------------- Kernel 2: row-direction cumsums ----------------------------
__global__ __launch_bounds__(256) void k_integral() {
    const int j = blockIdx.x;
    const int h = blockIdx.y;
    __shared__ float ksh[HW * D];
    __shared__ float vsh[HW * D];
    const int tid = threadIdx.x;
#pragma unroll
    for (int r = 0; r < 8; r++) {
        int l = tid + r * 256;
        int i = l >> 5, a = l & 31;
        size_t gi = ((size_t)(h * NTOK + i * HW + j)) * D + a;
        ksh[l] = g_K[gi];
        vsh[l] = g_V[gi];
    }
    __syncthreads();
    const int a = tid >> 3;
    const int b = (tid & 7) * 4;
    float4 acc = make_float4(0.f, 0.f, 0.f, 0.f);
    float kacc = 0.f;
    for (int i = 0; i < HW; i++) {
        float kv = ksh[i * D + a];
        float4 vv = *(const float4*)&vsh[i * D + b];
        acc.x += kv * vv.x; acc.y += kv * vv.y; acc.z += kv * vv.z; acc.w += kv * vv.w;
        *(float4*)&g_U[(((size_t)(h * HW + i)) * HW + j) * (D * D) + tid * 4] = acc;
        if (tid < 32) {
            kacc += ksh[i * D + tid];
            g_Kc[((h * HW + i) * HW + j) * D + tid] = kacc;
        }
    }
}

// ---------------- Kernel 3: column scan of g_Kc -> full 2D k integral --------
__global__ __launch_bounds__(256) void k_scan() {
    const int i = blockIdx.x;
    const int h = blockIdx.y;
    __shared__ float s[HW * D];
    float* row = g_Kc + (size_t)(h * HW + i) * HW * D;
    const int tid = threadIdx.x;
#pragma unroll
    for (int r = 0; r < 8; r++) s[tid + r * 256] = row[tid + r * 256];
    __syncthreads();
    if (tid < 32) {
        float acc = 0.f;
        for (int j = 0; j < HW; j++) {
            acc += s[j * D + tid];
            s[j * D + tid] = acc;
        }
    }
    __syncthreads();
#pragma unroll
    for (int r = 0; r < 8; r++) row[tid + r * 256] = s[tid + r * 256];
}

// ---------------- Kernel 4: windowed linear attention sweep (unchanged) ------
__global__ __launch_bounds__(256) void k_attn() {
    extern __shared__ float smem[];
    float* qsh   = smem;                 // 2048 floats
    float* numsh = smem + 2048;          // 2048
    float* Msh   = smem + 4096;          // 8 * 1024
    float* densh = smem + 4096 + 8192;   // 64

    const int ii = blockIdx.x;
    const int win = blockIdx.y;
    const int h = blockIdx.z;
    const int r = (win == 0) ? 32 : (win == 1) ? 16 : 8;

    const int tid = threadIdx.x;
    const int warp = tid >> 5, lane = tid & 31;

#pragma unroll
    for (int rr = 0; rr < 8; rr++) {
        int l = tid + rr * 256;
        qsh[l] = g_Q[((size_t)(h * NTOK + ii * HW)) * D + l];
        numsh[l] = 0.f;
    }

    const int x2 = min(ii + r, HW - 1);
    const int xl = ii - r - 1;
    const bool hasl = (xl >= 0);
    const float* Uh = g_U + ((size_t)(h * HW + x2)) * HW * (D * D) + tid * 4;
    const float* Ul = g_U + ((size_t)(h * HW + max(xl, 0))) * HW * (D * D) + tid * 4;

    float4 sh[MB], sl[MB];
#pragma unroll
    for (int u = 0; u < MB; u++) {
        sh[u] = *(const float4*)&Uh[(size_t)u * (D * D)];
        if (hasl) sl[u] = *(const float4*)&Ul[(size_t)u * (D * D)];
    }
    float4 mreg = make_float4(0.f, 0.f, 0.f, 0.f);
    int rot = 0;
    __syncthreads();

    for (int j0 = 0; j0 < HW; j0 += MB) {
#pragma unroll
        for (int u = 0; u < MB; u++) {
            const int j = j0 + u;
            float4 dd = sh[u];
            if (hasl) { dd.x -= sl[u].x; dd.y -= sl[u].y; dd.z -= sl[u].z; dd.w -= sl[u].w; }
            mreg.x += dd.x; mreg.y += dd.y; mreg.z += dd.z; mreg.w += dd.w;
            *(float4*)&Msh[((j & 7) << 10) + tid * 4] = mreg;
            if (j + MB < HW) {
                size_t off = (size_t)(j + MB) * (D * D);
                sh[u] = *(const float4*)&Uh[off];
                if (hasl) sl[u] = *(const float4*)&Ul[off];
            }
        }
        __syncthreads();

#pragma unroll
        for (int u = 0; u < MB; u++) {
            const int j = j0 + u;
            const int nplus = (j == HW - 1) ? (r + 1) : ((j >= r) ? 1 : 0);
            const int jjp0  = (j == HW - 1) ? (HW - 1 - r) : (j - r);
            const int hasminus = (j + r + 1 <= HW - 1) ? 1 : 0;
            const int nev = nplus + hasminus;
            const int npairs = (nev + 1) >> 1;
            const float* M = Msh + ((j & 7) << 10);
            int w0 = warp - rot; if (w0 < 0) w0 += 8;
            for (int p = w0; p < npairs; p += 8) {
                const int e0 = 2 * p, e1 = 2 * p + 1;
                const int jjA = (e0 < nplus) ? jjp0 + e0 : j + r + 1;
                const float sgnA = (e0 < nplus) ? 1.f : -1.f;
                const bool hasB = (e1 < nev);
                const int jjB = hasB ? ((e1 < nplus) ? jjp0 + e1 : j + r + 1) : jjA;
                const float sgnB = (e1 < nplus) ? 1.f : -1.f;
                const float* qA = &qsh[jjA * D];
                const float* qB = &qsh[jjB * D];
                float rA = 0.f, rB = 0.f;
#pragma unroll
                for (int a = 0; a < 32; a += 4) {
                    float4 qa = *(const float4*)&qA[a];
                    float4 qb = *(const float4*)&qB[a];
                    float m0 = M[(a + 0) * 32 + lane];
                    float m1 = M[(a + 1) * 32 + lane];
                    float m2 = M[(a + 2) * 32 + lane];
                    float m3 = M[(a + 3) * 32 + lane];
                    rA += qa.x * m0 + qa.y * m1 + qa.z * m2 + qa.w * m3;
                    rB += qb.x * m0 + qb.y * m1 + qb.z * m2 + qb.w * m3;
                }
                numsh[jjA * D + lane] += sgnA * rA;
                if (hasB) numsh[jjB * D + lane] += sgnB * rB;
            }
            rot += npairs; rot &= 7;
        }
    }
    __syncthreads();

    const float* S2 = g_Kc + (size_t)(h * HW + x2) * HW * D;
    const float* Sl = g_Kc + (size_t)(h * HW + max(xl, 0)) * HW * D;
    for (int jj = warp; jj < HW; jj += 8) {
        const int y2 = min(jj + r, HW - 1);
        const int yl = jj - r - 1;
        float v = S2[y2 * D + lane];
        if (hasl) v -= Sl[y2 * D + lane];
        if (yl >= 0) {
            v -= S2[yl * D + lane];
            if (hasl) v += Sl[yl * D + lane];
        }
        float p = qsh[jj * D + lane] * v;
#pragma unroll
        for (int off = 16; off; off >>= 1) p += __shfl_xor_sync(0xffffffffu, p, off);
        if (lane == 0) densh[jj] = p;
    }
    __syncthreads();

#pragma unroll
    for (int rr = 0; rr < 8; rr++) {
        int l = tid + rr * 256;
        int jj = l >> 5, e = l & 31;
        float o = numsh[l] / (densh[jj] + 1e-6f);
        g_Cat[(size_t)(ii * HW + jj) * INCDIM + win * DIMX + h * D + e] = o;
    }
}

// ---------------- Kernel 5: output GEMM (split-bf16 tensor core) + bias ------
// out[4096 x 256] = Cat @ wo + bo; BM=64, BN=64, KC=32; 8 warps, 32x16/warp.
__global__ __launch_bounds__(256) void k_out_mma(const float* __restrict__ bo,
                                                 float* __restrict__ out) {
    __shared__ __nv_bfloat16 Ah[64 * LDS], Al[64 * LDS];
    __shared__ __nv_bfloat16 Bh[64 * LDS], Bl[64 * LDS];
    const int row0 = blockIdx.x * 64;
    const int col0 = blockIdx.y * 64;
    const int tid = threadIdx.x;
    const int warp = tid >> 5, lane = tid & 31;
    const int wm = warp & 1, wn = warp >> 1;
    const int group = lane >> 2, tg = lane & 3;
    const int lr = lane & 15, lc = lane >> 4;

    float4 acc[2][2];
#pragma unroll
    for (int t = 0; t < 2; t++)
#pragma unroll
        for (int nt = 0; nt < 2; nt++) acc[t][nt] = make_float4(0.f, 0.f, 0.f, 0.f);

    const int m = tid >> 2, q = tid & 3;     // 64 rows x 4 quads of 8 bf16
    for (int k0 = 0; k0 < INCDIM; k0 += 32) {
        *(uint4*)&Ah[m * LDS + q * 8] = *(const uint4*)&g_ch[(size_t)(row0 + m) * INCDIM + k0 + q * 8];
        *(uint4*)&Al[m * LDS + q * 8] = *(const uint4*)&g_cl[(size_t)(row0 + m) * INCDIM + k0 + q * 8];
        *(uint4*)&Bh[m * LDS + q * 8] = *(const uint4*)&g_woh[(size_t)(col0 + m) * INCDIM + k0 + q * 8];
        *(uint4*)&Bl[m * LDS + q * 8] = *(const uint4*)&g_wol[(size_t)(col0 + m) * INCDIM + k0 + q * 8];
        __syncthreads();
#pragma unroll
        for (int kk = 0; kk < 32; kk += 16) {
            uint32_t ah[2][4], al[2][4];
#pragma unroll
            for (int t = 0; t < 2; t++) {
                const __nv_bfloat16* pa = &Ah[(wm * 32 + t * 16 + lr) * LDS + kk + lc * 8];
                const __nv_bfloat16* pl = &Al[(wm * 32 + t * 16 + lr) * LDS + kk + lc * 8];
                ldm4(ah[t][0], ah[t][1], ah[t][2], ah[t][3], pa);
                ldm4(al[t][0], al[t][1], al[t][2], al[t][3], pl);
            }
#pragma unroll
            for (int nt = 0; nt < 2; nt++) {
                int bi = (wn * 16 + nt * 8 + group) * LDS + kk + tg * 2;
                uint32_t bh0 = *(const uint32_t*)&Bh[bi];
                uint32_t bh1 = *(const uint32_t*)&Bh[bi + 8];
                uint32_t bl0 = *(const uint32_t*)&Bl[bi];
                uint32_t bl1 = *(const uint32_t*)&Bl[bi + 8];
#pragma unroll
                for (int t = 0; t < 2; t++) {
                    mma_bf16(acc[t][nt], ah[t][0], ah[t][1], ah[t][2], ah[t][3], bh0, bh1);
                    mma_bf16(acc[t][nt], ah[t][0], ah[t][1], ah[t][2], ah[t][3], bl0, bl1);
                    mma_bf16(acc[t][nt], al[t][0], al[t][1], al[t][2], al[t][3], bh0, bh1);
                }
            }
        }
        __syncthreads();
    }

#pragma unroll
    for (int t = 0; t < 2; t++) {
#pragma unroll
        for (int nt = 0; nt < 2; nt++) {
            int row = row0 + wm * 32 + t * 16 + group;
            int col = col0 + wn * 16 + nt * 8 + tg * 2;
            float b0 = bo[col], b1 = bo[col + 1];
            float* p0 = &out[(size_t)row * DIMX + col];
            p0[0] = acc[t][nt].x + b0;
            p0[1] = acc[t][nt].y + b1;
            float* p1 = &out[(size_t)(row + 8) * DIMX + col];
            p1[0] = acc[t][nt].z + b0;
            p1[1] = acc[t][nt].w + b1;
        }
    }
}

// ---------------- launch -----------------------------------------------------
#define ATTN_SMEM ((2048 + 2048 + 8192 + 64) * 4)

extern "C" void kernel_launch(void* const* d_in, const int* in_sizes, int n_in,
                              void* d_out, int out_size) {
    const float* x  = (const float*)d_in[0];
    const float* wq = (const float*)d_in[1];
    const float* wk = (const float*)d_in[2];
    const float* wv = (const float*)d_in[3];
    const float* wo = (const float*)d_in[4];
    const float* bo = (const float*)d_in[5];
    float* out = (float*)d_out;

    cudaFuncSetAttribute(k_attn, cudaFuncAttributeMaxDynamicSharedMemorySize, ATTN_SMEM);

    k_split_x<<<(NTOK * DIMX / 4) / 256, 256>>>(x);
    k_split_w<<<(INCDIM * DIMX) / 256, 256>>>(wq, wk, wv);
    k_split_wo<<<(DIMX * INCDIM) / 256, 256>>>(wo);
    k_qkv_mma<<<dim3(NTOK / 128, INCDIM / 64), 256>>>();
    k_integral<<<dim3(HW, HEADS), 256>>>();
    k_scan<<<dim3(HW, HEADS), 256>>>();
    k_attn<<<dim3(HW, 3, HEADS), 256, ATTN_SMEM>>>();
    k_split_cat<<<((NTOK * INCDIM) / 4) / 256, 256>>>();
    k_out_mma<<<dim3(NTOK / 64, DIMX / 64), 256>>>(bo, out);
}

// round 12
// speedup vs baseline: 1.4758x; 1.0282x over previous
#include <cuda_runtime.h>
#include <cuda_bf16.h>
#include <stdint.h>
#include <math.h>

#define HEADS 8
#define HW 64
#define D 32
#define NTOK 4096
#define DIMX 256
#define INCDIM 768
#define MB 2
#define LDS 40   // padded smem row stride (bf16) -> conflict-free ldmatrix

// ---------------- scratch (static device globals; no allocation) -------------
__device__ float g_Q[HEADS * NTOK * D];                 // 4 MB
__device__ float g_K[HEADS * NTOK * D];                 // 4 MB
__device__ float g_V[HEADS * NTOK * D];                 // 4 MB
__device__ float g_U[(size_t)HEADS * HW * HW * D * D];  // 134 MB row-cumsum of k (x) v
__device__ float g_Kc[HEADS * HW * HW * D];             // 4 MB k integral (row, then 2D)
__device__ float g_Cat[(size_t)NTOK * INCDIM];          // 12.6 MB window-output concat

// split-bf16 operands (hi + lo decomposition of fp32)
__device__ __nv_bfloat16 g_xh[NTOK * DIMX], g_xl[NTOK * DIMX];         // x rows [n][k]
__device__ __nv_bfloat16 g_wh[INCDIM * DIMX], g_wl[INCDIM * DIMX];     // [n][k] = W^T (qkv)
__device__ __nv_bfloat16 g_woh[DIMX * INCDIM], g_wol[DIMX * INCDIM];   // [n][k] = wo^T
__device__ __nv_bfloat16 g_ch[(size_t)NTOK * INCDIM], g_cl[(size_t)NTOK * INCDIM]; // Cat [n][k]

// ---------------- helpers ----------------------------------------------------
__device__ __forceinline__ void mma_bf16(float4& d, uint32_t a0, uint32_t a1,
                                         uint32_t a2, uint32_t a3,
                                         uint32_t b0, uint32_t b1) {
    asm volatile(
        "mma.sync.aligned.m16n8k16.row.col.f32.bf16.bf16.f32 "
        "{%0,%1,%2,%3}, {%4,%5,%6,%7}, {%8,%9}, {%0,%1,%2,%3};"
        : "+f"(d.x), "+f"(d.y), "+f"(d.z), "+f"(d.w)
        : "r"(a0), "r"(a1), "r"(a2), "r"(a3), "r"(b0), "r"(b1));
}

__device__ __forceinline__ void ldm4(uint32_t& r0, uint32_t& r1, uint32_t& r2,
                                     uint32_t& r3, const __nv_bfloat16* p) {
    uint32_t addr = (uint32_t)__cvta_generic_to_shared(p);
    asm volatile("ldmatrix.sync.aligned.m8n8.x4.shared.b16 {%0,%1,%2,%3}, [%4];"
                 : "=r"(r0), "=r"(r1), "=r"(r2), "=r"(r3) : "r"(addr));
}

__device__ __forceinline__ void split2(float v, __nv_bfloat16& h, __nv_bfloat16& l) {
    h = __float2bfloat16(v);
    l = __float2bfloat16(v - __bfloat162float(h));
}

__device__ __forceinline__ void cp16(uint32_t s, const void* g) {
    asm volatile("cp.async.cg.shared.global [%0], [%1], 16;" :: "r"(s), "l"(g));
}
__device__ __forceinline__ void cp_commit() {
    asm volatile("cp.async.commit_group;");
}
template <int N>
__device__ __forceinline__ void cp_wait() {
    asm volatile("cp.async.wait_group %0;" :: "n"(N));
}

// ---------------- split kernels ----------------------------------------------
__global__ __launch_bounds__(256) void k_split_x(const float* __restrict__ x) {
    int i = blockIdx.x * 256 + threadIdx.x;        // float4 index
    float4 v = ((const float4*)x)[i];
    int o = i * 4;
    split2(v.x, g_xh[o + 0], g_xl[o + 0]);
    split2(v.y, g_xh[o + 1], g_xl[o + 1]);
    split2(v.z, g_xh[o + 2], g_xl[o + 2]);
    split2(v.w, g_xh[o + 3], g_xl[o + 3]);
}

__global__ __launch_bounds__(256) void k_split_w(const float* __restrict__ wq,
                                                 const float* __restrict__ wk,
                                                 const float* __restrict__ wv) {
    int o = blockIdx.x * 256 + threadIdx.x;        // o = n*256 + k, n in [0,768)
    int n = o >> 8, k = o & 255;
    const float* W = (n < 256) ? wq : (n < 512) ? wk : wv;
    float v = W[(k << 8) + (n & 255)];
    split2(v, g_wh[o], g_wl[o]);
}

__global__ __launch_bounds__(256) void k_split_wo(const float* __restrict__ wo) {
    int o = blockIdx.x * 256 + threadIdx.x;        // o = n*768 + k, n in [0,256)
    int n = o / INCDIM, k = o - n * INCDIM;
    float v = wo[k * DIMX + n];
    split2(v, g_woh[o], g_wol[o]);
}

__global__ __launch_bounds__(256) void k_split_cat() {
    int i = blockIdx.x * 256 + threadIdx.x;        // float4 index
    float4 v = ((const float4*)g_Cat)[i];
    size_t o = (size_t)i * 4;
    split2(v.x, g_ch[o + 0], g_cl[o + 0]);
    split2(v.y, g_ch[o + 1], g_cl[o + 1]);
    split2(v.z, g_ch[o + 2], g_cl[o + 2]);
    split2(v.w, g_ch[o + 3], g_cl[o + 3]);
}

// ---------------- Kernel 1: QKV GEMM (split-bf16, cp.async 2-stage) + ELU ----
// C[4096 x 768] = x @ [wq|wk|wv]; BM=128, BN=64, KC=32; 8 warps, 32x32/warp.
// Dynamic smem: 2 stages x (Ah 128x40 | Al 128x40 | Bh 64x40 | Bl 64x40) bf16.
#define QKV_STG (128 * LDS + 128 * LDS + 64 * LDS + 64 * LDS)   // 15360 bf16
#define QKV_SMEM (2 * QKV_STG * 2)                               // 61440 B

__global__ __launch_bounds__(256) void k_qkv_mma() {
    extern __shared__ __nv_bfloat16 qsm[];
    const int row0 = blockIdx.x * 128;
    const int col0g = blockIdx.y * 64;     // 0..767
    const int part = col0g >> 8;
    const int tid = threadIdx.x;
    const int warp = tid >> 5, lane = tid & 31;
    const int wm = warp & 3, wn = warp >> 2;
    const int group = lane >> 2, tg = lane & 3;
    const int lr = lane & 15, lc = lane >> 4;

    // per-thread load coords
    const int am = tid >> 1, ah_ = tid & 1;        // A row, half
    const int bt = tid & 127;
    const int bn = bt >> 1, bh_ = bt & 1;          // B row, half
    const bool bhi = (tid < 128);

    auto issue_stage = [&](int s, int k0) {
        __nv_bfloat16* Ah = qsm + s * QKV_STG;
        __nv_bfloat16* Al = Ah + 128 * LDS;
        __nv_bfloat16* Bh = Al + 128 * LDS;
        __nv_bfloat16* Bl = Bh + 64 * LDS;
        uint32_t da = (uint32_t)__cvta_generic_to_shared(&Ah[am * LDS + ah_ * 16]);
        cp16(da,      &g_xh[((row0 + am) << 8) + k0 + ah_ * 16]);
        cp16(da + 16, &g_xh[((row0 + am) << 8) + k0 + ah_ * 16 + 8]);
        uint32_t dl = (uint32_t)__cvta_generic_to_shared(&Al[am * LDS + ah_ * 16]);
        cp16(dl,      &g_xl[((row0 + am) << 8) + k0 + ah_ * 16]);
        cp16(dl + 16, &g_xl[((row0 + am) << 8) + k0 + ah_ * 16 + 8]);
        const __nv_bfloat16* gsrc = bhi ? g_wh : g_wl;
        __nv_bfloat16* dstb = bhi ? Bh : Bl;
        uint32_t db = (uint32_t)__cvta_generic_to_shared(&dstb[bn * LDS + bh_ * 16]);
        cp16(db,      &gsrc[(col0g + bn) * DIMX + k0 + bh_ * 16]);
        cp16(db + 16, &gsrc[(col0g + bn) * DIMX + k0 + bh_ * 16 + 8]);
        cp_commit();
    };

    float4 acc[2][4];
#pragma unroll
    for (int t = 0; t < 2; t++)
#pragma unroll
        for (int nt = 0; nt < 4; nt++) acc[t][nt] = make_float4(0.f, 0.f, 0.f, 0.f);

    issue_stage(0, 0);
    for (int it = 0; it < 8; it++) {
        if (it + 1 < 8) issue_stage((it + 1) & 1, (it + 1) * 32);
        if (it + 1 < 8) cp_wait<1>(); else cp_wait<0>();
        __syncthreads();
        const __nv_bfloat16* Ah = qsm + (it & 1) * QKV_STG;
        const __nv_bfloat16* Al = Ah + 128 * LDS;
        const __nv_bfloat16* Bh = Al + 128 * LDS;
        const __nv_bfloat16* Bl = Bh + 64 * LDS;
#pragma unroll
        for (int kk = 0; kk < 32; kk += 16) {
            uint32_t ahf[2][4], alf[2][4];
#pragma unroll
            for (int t = 0; t < 2; t++) {
                ldm4(ahf[t][0], ahf[t][1], ahf[t][2], ahf[t][3],
                     &Ah[(wm * 32 + t * 16 + lr) * LDS + kk + lc * 8]);
                ldm4(alf[t][0], alf[t][1], alf[t][2], alf[t][3],
                     &Al[(wm * 32 + t * 16 + lr) * LDS + kk + lc * 8]);
            }
#pragma unroll
            for (int nt = 0; nt < 4; nt++) {
                int bi = (wn * 32 + nt * 8 + group) * LDS + kk + tg * 2;
                uint32_t bh0 = *(const uint32_t*)&Bh[bi];
                uint32_t bh1 = *(const uint32_t*)&Bh[bi + 8];
                uint32_t bl0 = *(const uint32_t*)&Bl[bi];
                uint32_t bl1 = *(const uint32_t*)&Bl[bi + 8];
#pragma unroll
                for (int t = 0; t < 2; t++) {
                    mma_bf16(acc[t][nt], ahf[t][0], ahf[t][1], ahf[t][2], ahf[t][3], bh0, bh1);
                    mma_bf16(acc[t][nt], ahf[t][0], ahf[t][1], ahf[t][2], ahf[t][3], bl0, bl1);
                    mma_bf16(acc[t][nt], alf[t][0], alf[t][1], alf[t][2], alf[t][3], bh0, bh1);
                }
            }
        }
        __syncthreads();
    }

    float* dst = (part == 0) ? g_Q : (part == 1) ? g_K : g_V;
    const int colbase = (col0g & 255) + wn * 32;
#pragma unroll
    for (int t = 0; t < 2; t++) {
#pragma unroll
        for (int nt = 0; nt < 4; nt++) {
            int row = row0 + wm * 32 + t * 16 + group;
            int colm = colbase + nt * 8 + tg * 2;
            int h = colm >> 5, e = colm & 31;
            float v0 = acc[t][nt].x, v1 = acc[t][nt].y;
            float v2 = acc[t][nt].z, v3 = acc[t][nt].w;
            if (part < 2) {
                v0 = (v0 > 0.f) ? (v0 + 1.000001f) : (expf(v0) + 1e-6f);
                v1 = (v1 > 0.f) ? (v1 + 1.000001f) : (expf(v1) + 1e-6f);
                v2 = (v2 > 0.f) ? (v2 + 1.000001f) : (expf(v2) + 1e-6f);
                v3 = (v3 > 0.f) ? (v3 + 1.000001f) : (expf(v3) + 1e-6f);
            }
            float* p0 = &dst[((size_t)(h * NTOK + row)) * D + e];
            p0[0] = v0; p0[1] = v1;
            float* p1 = &dst[((size_t)(h * NTOK + row + 8)) * D + e];
            p1[0] = v2; p1[1] = v3;
        }
    }
}

// ---------------- Kernel 2: row-direction cumsums ----------------------------
__global__ __launch_bounds__(256) void k_integral() {
    const int j = blockIdx.x;
    const int h = blockIdx.y;
    __shared__ float ksh[HW * D];
    __shared__ float vsh[HW * D];
    const int tid = threadIdx.x;
#pragma unroll
    for (int r = 0; r < 8; r++) {
        int l = tid + r * 256;
        int i = l >> 5, a = l & 31;
        size_t gi = ((size_t)(h * NTOK + i * HW + j)) * D + a;
        ksh[l] = g_K[gi];
        vsh[l] = g_V[gi];
    }
    __syncthreads();
    const int a = tid >> 3;
    const int b = (tid & 7) * 4;
    float4 acc = make_float4(0.f, 0.f, 0.f, 0.f);
    float kacc = 0.f;
    for (int i = 0; i < HW; i++) {
        float kv = ksh[i * D + a];
        float4 vv = *(const float4*)&vsh[i * D + b];
        acc.x += kv * vv.x; acc.y += kv * vv.y; acc.z += kv * vv.z; acc.w += kv * vv.w;
        *(float4*)&g_U[(((size_t)(h * HW + i)) * HW + j) * (D * D) + tid * 4] = acc;
        if (tid < 32) {
            kacc += ksh[i * D + tid];
            g_Kc[((h * HW + i) * HW + j) * D + tid] = kacc;
        }
    }
}

// ---------------- Kernel 3: column scan of g_Kc -> full 2D k integral --------
__global__ __launch_bounds__(256) void k_scan() {
    const int i = blockIdx.x;
    const int h = blockIdx.y;
    __shared__ float s[HW * D];
    float* row = g_Kc + (size_t)(h * HW + i) * HW * D;
    const int tid = threadIdx.x;
#pragma unroll
    for (int r = 0; r < 8; r++) s[tid + r * 256] = row[tid + r * 256];
    __syncthreads();
    if (tid < 32) {
        float acc = 0.f;
        for (int j = 0; j < HW; j++) {
            acc += s[j * D + tid];
            s[j * D + tid] = acc;
        }
    }
    __syncthreads();
#pragma unroll
    for (int r = 0; r < 8; r++) row[tid + r * 256] = s[tid + r * 256];
}

// ---------------- Kernel 4: windowed linear attention sweep ------------------
// MB=2 staging (fewer regs) + forced 4 blocks/SM for L1-latency hiding.
__global__ __launch_bounds__(256, 4) void k_attn() {
    extern __shared__ float smem[];
    float* qsh   = smem;                 // 2048 floats
    float* numsh = smem + 2048;          // 2048
    float* Msh   = smem + 4096;          // 8 * 1024
    float* densh = smem + 4096 + 8192;   // 64

    const int ii = blockIdx.x;
    const int win = blockIdx.y;
    const int h = blockIdx.z;
    const int r = (win == 0) ? 32 : (win == 1) ? 16 : 8;

    const int tid = threadIdx.x;
    const int warp = tid >> 5, lane = tid & 31;

#pragma unroll
    for (int rr = 0; rr < 8; rr++) {
        int l = tid + rr * 256;
        qsh[l] = g_Q[((size_t)(h * NTOK + ii * HW)) * D + l];
        numsh[l] = 0.f;
    }

    const int x2 = min(ii + r, HW - 1);
    const int xl = ii - r - 1;
    const bool hasl = (xl >= 0);
    const float* Uh = g_U + ((size_t)(h * HW + x2)) * HW * (D * D) + tid * 4;
    const float* Ul = g_U + ((size_t)(h * HW + max(xl, 0))) * HW * (D * D) + tid * 4;

    float4 sh[MB], sl[MB];
#pragma unroll
    for (int u = 0; u < MB; u++) {
        sh[u] = *(const float4*)&Uh[(size_t)u * (D * D)];
        if (hasl) sl[u] = *(const float4*)&Ul[(size_t)u * (D * D)];
    }
    float4 mreg = make_float4(0.f, 0.f, 0.f, 0.f);
    int rot = 0;
    __syncthreads();

    for (int j0 = 0; j0 < HW; j0 += MB) {
#pragma unroll
        for (int u = 0; u < MB; u++) {
            const int j = j0 + u;
            float4 dd = sh[u];
            if (hasl) { dd.x -= sl[u].x; dd.y -= sl[u].y; dd.z -= sl[u].z; dd.w -= sl[u].w; }
            mreg.x += dd.x; mreg.y += dd.y; mreg.z += dd.z; mreg.w += dd.w;
            *(float4*)&Msh[((j & 7) << 10) + tid * 4] = mreg;
            if (j + MB < HW) {
                size_t off = (size_t)(j + MB) * (D * D);
                sh[u] = *(const float4*)&Uh[off];
                if (hasl) sl[u] = *(const float4*)&Ul[off];
            }
        }
        __syncthreads();

#pragma unroll
        for (int u = 0; u < MB; u++) {
            const int j = j0 + u;
            const int nplus = (j == HW - 1) ? (r + 1) : ((j >= r) ? 1 : 0);
            const int jjp0  = (j == HW - 1) ? (HW - 1 - r) : (j - r);
            const int hasminus = (j + r + 1 <= HW - 1) ? 1 : 0;
            const int nev = nplus + hasminus;
            const int npairs = (nev + 1) >> 1;
            const float* M = Msh + ((j & 7) << 10);
            int w0 = warp - rot; if (w0 < 0) w0 += 8;
            for (int p = w0; p < npairs; p += 8) {
                const int e0 = 2 * p, e1 = 2 * p + 1;
                const int jjA = (e0 < nplus) ? jjp0 + e0 : j + r + 1;
                const float sgnA = (e0 < nplus) ? 1.f : -1.f;
                const bool hasB = (e1 < nev);
                const int jjB = hasB ? ((e1 < nplus) ? jjp0 + e1 : j + r + 1) : jjA;
                const float sgnB = (e1 < nplus) ? 1.f : -1.f;
                const float* qA = &qsh[jjA * D];
                const float* qB = &qsh[jjB * D];
                float rA = 0.f, rB = 0.f;
#pragma unroll
                for (int a = 0; a < 32; a += 4) {
                    float4 qa = *(const float4*)&qA[a];
                    float4 qb = *(const float4*)&qB[a];
                    float m0 = M[(a + 0) * 32 + lane];
                    float m1 = M[(a + 1) * 32 + lane];
                    float m2 = M[(a + 2) * 32 + lane];
                    float m3 = M[(a + 3) * 32 + lane];
                    rA += qa.x * m0 + qa.y * m1 + qa.z * m2 + qa.w * m3;
                    rB += qb.x * m0 + qb.y * m1 + qb.z * m2 + qb.w * m3;
                }
                numsh[jjA * D + lane] += sgnA * rA;
                if (hasB) numsh[jjB * D + lane] += sgnB * rB;
            }
            rot += npairs; rot &= 7;
        }
    }
    __syncthreads();

    const float* S2 = g_Kc + (size_t)(h * HW + x2) * HW * D;
    const float* Sl = g_Kc + (size_t)(h * HW + max(xl, 0)) * HW * D;
    for (int jj = warp; jj < HW; jj += 8) {
        const int y2 = min(jj + r, HW - 1);
        const int yl = jj - r - 1;
        float v = S2[y2 * D + lane];
        if (hasl) v -= Sl[y2 * D + lane];
        if (yl >= 0) {
            v -= S2[yl * D + lane];
            if (hasl) v += Sl[yl * D + lane];
        }
        float p = qsh[jj * D + lane] * v;
#pragma unroll
        for (int off = 16; off; off >>= 1) p += __shfl_xor_sync(0xffffffffu, p, off);
        if (lane == 0) densh[jj] = p;
    }
    __syncthreads();

#pragma unroll
    for (int rr = 0; rr < 8; rr++) {
        int l = tid + rr * 256;
        int jj = l >> 5, e = l & 31;
        float o = numsh[l] / (densh[jj] + 1e-6f);
        g_Cat[(size_t)(ii * HW + jj) * INCDIM + win * DIMX + h * D + e] = o;
    }
}

// ---------------- Kernel 5: output GEMM (split-bf16, cp.async 2-stage) -------
// out[4096 x 256] = Cat @ wo + bo; BM=64, BN=64, KC=32; 8 warps, 32x16/warp.
__global__ __launch_bounds__(256) void k_out_mma(const float* __restrict__ bo,
                                                 float* __restrict__ out) {
    __shared__ __nv_bfloat16 S[2][4 * 64 * LDS];   // per stage: Ah|Al|Bh|Bl
    const int row0 = blockIdx.x * 64;
    const int col0 = blockIdx.y * 64;
    const int tid = threadIdx.x;
    const int warp = tid >> 5, lane = tid & 31;
    const int wm = warp & 1, wn = warp >> 1;
    const int group = lane >> 2, tg = lane & 3;
    const int lr = lane & 15, lc = lane >> 4;
    const int m = tid >> 2, q = tid & 3;

    auto issue_stage = [&](int s, int k0) {
        __nv_bfloat16* Ah = S[s];
        __nv_bfloat16* Al = Ah + 64 * LDS;
        __nv_bfloat16* Bh = Al + 64 * LDS;
        __nv_bfloat16* Bl = Bh + 64 * LDS;
        uint32_t off = (uint32_t)(m * LDS + q * 8);
        cp16((uint32_t)__cvta_generic_to_shared(&Ah[off]), &g_ch[(size_t)(row0 + m) * INCDIM + k0 + q * 8]);
        cp16((uint32_t)__cvta_generic_to_shared(&Al[off]), &g_cl[(size_t)(row0 + m) * INCDIM + k0 + q * 8]);
        cp16((uint32_t)__cvta_generic_to_shared(&Bh[off]), &g_woh[(size_t)(col0 + m) * INCDIM + k0 + q * 8]);
        cp16((uint32_t)__cvta_generic_to_shared(&Bl[off]), &g_wol[(size_t)(col0 + m) * INCDIM + k0 + q * 8]);
        cp_commit();
    };

    float4 acc[2][2];
#pragma unroll
    for (int t = 0; t < 2; t++)
#pragma unroll
        for (int nt = 0; nt < 2; nt++) acc[t][nt] = make_float4(0.f, 0.f, 0.f, 0.f);

    issue_stage(0, 0);
    for (int it = 0; it < 24; it++) {
        if (it + 1 < 24) issue_stage((it + 1) & 1, (it + 1) * 32);
        if (it + 1 < 24) cp_wait<1>(); else cp_wait<0>();
        __syncthreads();
        const __nv_bfloat16* Ah = S[it & 1];
        const __nv_bfloat16* Al = Ah + 64 * LDS;
        const __nv_bfloat16* Bh = Al + 64 * LDS;
        const __nv_bfloat16* Bl = Bh + 64 * LDS;
#pragma unroll
        for (int kk = 0; kk < 32; kk += 16) {
            uint32_t ahf[2][4], alf[2][4];
#pragma unroll
            for (int t = 0; t < 2; t++) {
                ldm4(ahf[t][0], ahf[t][1], ahf[t][2], ahf[t][3],
                     &Ah[(wm * 32 + t * 16 + lr) * LDS + kk + lc * 8]);
                ldm4(alf[t][0], alf[t][1], alf[t][2], alf[t][3],
                     &Al[(wm * 32 + t * 16 + lr) * LDS + kk + lc * 8]);
            }
#pragma unroll
            for (int nt = 0; nt < 2; nt++) {
                int bi = (wn * 16 + nt * 8 + group) * LDS + kk + tg * 2;
                uint32_t bh0 = *(const uint32_t*)&Bh[bi];
                uint32_t bh1 = *(const uint32_t*)&Bh[bi + 8];
                uint32_t bl0 = *(const uint32_t*)&Bl[bi];
                uint32_t bl1 = *(const uint32_t*)&Bl[bi + 8];
#pragma unroll
                for (int t = 0; t < 2; t++) {
                    mma_bf16(acc[t][nt], ahf[t][0], ahf[t][1], ahf[t][2], ahf[t][3], bh0, bh1);
                    mma_bf16(acc[t][nt], ahf[t][0], ahf[t][1], ahf[t][2], ahf[t][3], bl0, bl1);
                    mma_bf16(acc[t][nt], alf[t][0], alf[t][1], alf[t][2], alf[t][3], bh0, bh1);
                }
            }
        }
        __syncthreads();
    }

#pragma unroll
    for (int t = 0; t < 2; t++) {
#pragma unroll
        for (int nt = 0; nt < 2; nt++) {
            int row = row0 + wm * 32 + t * 16 + group;
            int col = col0 + wn * 16 + nt * 8 + tg * 2;
            float b0 = bo[col], b1 = bo[col + 1];
            float* p0 = &out[(size_t)row * DIMX + col];
            p0[0] = acc[t][nt].x + b0;
            p0[1] = acc[t][nt].y + b1;
            float* p1 = &out[(size_t)(row + 8) * DIMX + col];
            p1[0] = acc[t][nt].z + b0;
            p1[1] = acc[t][nt].w + b1;
        }
    }
}

// ---------------- launch -----------------------------------------------------
#define ATTN_SMEM ((2048 + 2048 + 8192 + 64) * 4)

extern "C" void kernel_launch(void* const* d_in, const int* in_sizes, int n_in,
                              void* d_out, int out_size) {
    const float* x  = (const float*)d_in[0];
    const float* wq = (const float*)d_in[1];
    const float* wk = (const float*)d_in[2];
    const float* wv = (const float*)d_in[3];
    const float* wo = (const float*)d_in[4];
    const float* bo = (const float*)d_in[5];
    float* out = (float*)d_out;

    cudaFuncSetAttribute(k_attn, cudaFuncAttributeMaxDynamicSharedMemorySize, ATTN_SMEM);
    cudaFuncSetAttribute(k_qkv_mma, cudaFuncAttributeMaxDynamicSharedMemorySize, QKV_SMEM);

    k_split_x<<<(NTOK * DIMX / 4) / 256, 256>>>(x);
    k_split_w<<<(INCDIM * DIMX) / 256, 256>>>(wq, wk, wv);
    k_split_wo<<<(DIMX * INCDIM) / 256, 256>>>(wo);
    k_qkv_mma<<<dim3(NTOK / 128, INCDIM / 64), 256, QKV_SMEM>>>();
    k_integral<<<dim3(HW, HEADS), 256>>>();
    k_scan<<<dim3(HW, HEADS), 256>>>();
    k_attn<<<dim3(HW, 3, HEADS), 256, ATTN_SMEM>>>();
    k_split_cat<<<((NTOK * INCDIM) / 4) / 256, 256>>>();
    k_out_mma<<<dim3(NTOK / 64, DIMX / 64), 256>>>(bo, out);
}